// round 5
// baseline (speedup 1.0000x reference)
#include <cuda_runtime.h>
#include <math.h>

#define BB 4
#define TT 1024
#define DD 1024
#define HH 16
#define HSS 64

// Scratch (no cudaMalloc allowed)
__device__ float g_q[BB*HH*TT*HSS];
__device__ float g_k[BB*HH*TT*HSS];
__device__ float g_v[BB*HH*TT*HSS];
__device__ float g_att[BB*TT*DD];   // concat-head attention output [B*T, H*HS]

// ---------------------------------------------------------------------------
// tf32 helpers
// ---------------------------------------------------------------------------
__device__ __forceinline__ unsigned f2tf(float f) {
    unsigned r;
    asm("cvt.rna.tf32.f32 %0, %1;" : "=r"(r) : "f"(f));
    return r;
}
__device__ __forceinline__ float tf32r(float f) {
    return __uint_as_float(f2tf(f));
}

__device__ __forceinline__ void mma8(float* d, const unsigned* a, const unsigned* b) {
    asm volatile(
        "mma.sync.aligned.m16n8k8.row.col.f32.tf32.tf32.f32 "
        "{%0,%1,%2,%3}, {%4,%5,%6,%7}, {%8,%9}, {%0,%1,%2,%3};"
        : "+f"(d[0]), "+f"(d[1]), "+f"(d[2]), "+f"(d[3])
        : "r"(a[0]), "r"(a[1]), "r"(a[2]), "r"(a[3]),
          "r"(b[0]), "r"(b[1]));
}

// ---------------------------------------------------------------------------
// Pipelined 128x64 GEMM tile, tf32 mma. 256 threads = 8 warps (4m x 2n),
// warp tile 32x32, BK=32, double-buffered smem + register prefetch.
// As[m][36]  (bank = 4m+k  -> conflict-free frag loads)
// Bs[k][72]  (bank = 8k+n  -> conflict-free frag loads)
// ---------------------------------------------------------------------------
#define AS_STRIDE 36
#define BS_STRIDE 72
#define AS_WORDS  (128 * AS_STRIDE)    // 4608
#define BS_WORDS  (32 * BS_STRIDE)     // 2304
#define GEMM_SMEM ((AS_WORDS + BS_WORDS) * 2 * 4)   // 55296 bytes

__device__ __forceinline__ void sts_tiles(
    unsigned* __restrict__ As, unsigned* __restrict__ Bs,
    const float4* pa, const float4* pb, int tid)
{
#pragma unroll
    for (int i = 0; i < 4; i++) {
        int l   = tid + i * 256;
        int row = l >> 3;
        int k4  = l & 7;
        unsigned* p = &As[row * AS_STRIDE + k4 * 4];
        p[0] = f2tf(pa[i].x); p[1] = f2tf(pa[i].y);
        p[2] = f2tf(pa[i].z); p[3] = f2tf(pa[i].w);
    }
#pragma unroll
    for (int i = 0; i < 2; i++) {
        int l  = tid + i * 256;
        int kr = l >> 4;
        int n4 = l & 15;
        unsigned* p = &Bs[kr * BS_STRIDE + n4 * 4];
        p[0] = f2tf(pb[i].x); p[1] = f2tf(pb[i].y);
        p[2] = f2tf(pb[i].z); p[3] = f2tf(pb[i].w);
    }
}

__device__ __forceinline__ void lda_regs(
    float4* pa, const float* __restrict__ A, int lda, int k0, int tid)
{
#pragma unroll
    for (int i = 0; i < 4; i++) {
        int l   = tid + i * 256;
        int row = l >> 3;
        int k4  = l & 7;
        pa[i] = *reinterpret_cast<const float4*>(&A[(size_t)row * lda + k0 + k4 * 4]);
    }
}

__device__ __forceinline__ void mma_block_step(
    const unsigned* __restrict__ As, const unsigned* __restrict__ Bs,
    float acc[2][4][4], int wm, int wn, int lq, int lr)
{
#pragma unroll
    for (int kk = 0; kk < 4; kk++) {
        const int kc = kk * 8 + lr;
        unsigned a[2][4];
#pragma unroll
        for (int mf = 0; mf < 2; mf++) {
            int mr = wm * 32 + mf * 16 + lq;
            a[mf][0] = As[mr * AS_STRIDE + kc];
            a[mf][1] = As[(mr + 8) * AS_STRIDE + kc];
            a[mf][2] = As[mr * AS_STRIDE + kc + 4];
            a[mf][3] = As[(mr + 8) * AS_STRIDE + kc + 4];
        }
        unsigned b[4][2];
#pragma unroll
        for (int nf = 0; nf < 4; nf++) {
            int nc = wn * 32 + nf * 8 + lq;
            b[nf][0] = Bs[kc * BS_STRIDE + nc];
            b[nf][1] = Bs[(kc + 4) * BS_STRIDE + nc];
        }
#pragma unroll
        for (int mf = 0; mf < 2; mf++)
#pragma unroll
            for (int nf = 0; nf < 4; nf++)
                mma8(acc[mf][nf], a[mf], b[nf]);
    }
}

// ---------------------------------------------------------------------------
// Fused QKV projection: logical GEMM [4096 x 3072 x 1024], n-tile 64 = 1 head.
// grid (32, 48): nt 0..15 -> Q heads, 16..31 -> K heads, 32..47 -> V heads.
// ---------------------------------------------------------------------------
__global__ __launch_bounds__(256, 2) void qkv_kernel(
    const float* __restrict__ x,
    const float* __restrict__ Wq,
    const float* __restrict__ Wk,
    const float* __restrict__ Wv)
{
    extern __shared__ unsigned smw[];
    unsigned* As = smw;                         // 2 buffers
    unsigned* Bs = smw + 2 * AS_WORDS;

    const int mt = blockIdx.x;                  // 0..31
    const int nt = blockIdx.y;                  // 0..47
    const int which = nt >> 4;
    const int h     = nt & 15;

    const float* W = (which == 0 ? Wq : which == 1 ? Wk : Wv) + (size_t)h * DD * HSS;
    float* dst     = (which == 0 ? g_q : which == 1 ? g_k : g_v);
    const float* A = x + (size_t)mt * 128 * DD;

    const int tid  = threadIdx.x;
    const int lane = tid & 31;
    const int warp = tid >> 5;
    const int wm   = warp >> 1;                 // 0..3
    const int wn   = warp & 1;                  // 0..1
    const int lq   = lane >> 2;
    const int lr   = lane & 3;

    // B-load indices (per-head weight is row-major [D][HS], ldb = 64)
    const int bl0_k = tid >> 4;                 // 0..15
    const int bl0_n = (tid & 15) * 4;

    float acc[2][4][4];
#pragma unroll
    for (int mf = 0; mf < 2; mf++)
#pragma unroll
        for (int nf = 0; nf < 4; nf++)
#pragma unroll
            for (int j = 0; j < 4; j++) acc[mf][nf][j] = 0.f;

    float4 pa[4], pb[2];
    // prologue: k0 = 0
    lda_regs(pa, A, DD, 0, tid);
    pb[0] = *reinterpret_cast<const float4*>(&W[(size_t)bl0_k * HSS + bl0_n]);
    pb[1] = *reinterpret_cast<const float4*>(&W[(size_t)(bl0_k + 16) * HSS + bl0_n]);
    sts_tiles(As, Bs, pa, pb, tid);
    __syncthreads();

    for (int k0 = 0; k0 < DD; k0 += 32) {
        const int buf = (k0 >> 5) & 1;
        const bool more = (k0 + 32) < DD;
        if (more) {
            lda_regs(pa, A, DD, k0 + 32, tid);
            pb[0] = *reinterpret_cast<const float4*>(&W[(size_t)(k0 + 32 + bl0_k) * HSS + bl0_n]);
            pb[1] = *reinterpret_cast<const float4*>(&W[(size_t)(k0 + 48 + bl0_k) * HSS + bl0_n]);
        }
        mma_block_step(As + buf * AS_WORDS, Bs + buf * BS_WORDS, acc, wm, wn, lq, lr);
        if (more)
            sts_tiles(As + (1 - buf) * AS_WORDS, Bs + (1 - buf) * BS_WORDS, pa, pb, tid);
        __syncthreads();
    }

    // Epilogue -> g_{q,k,v}[(b*H+h)*T + t][hs]
#pragma unroll
    for (int mf = 0; mf < 2; mf++) {
#pragma unroll
        for (int nf = 0; nf < 4; nf++) {
            int row = wm * 32 + mf * 16 + lq;
            int hs  = wn * 32 + nf * 8 + 2 * lr;
#pragma unroll
            for (int half = 0; half < 2; half++) {
                int gr = mt * 128 + row + half * 8;
                int b = gr >> 10, t = gr & 1023;
                float* drow = dst + ((size_t)(b * HH + h) * TT + t) * HSS + hs;
                *reinterpret_cast<float2*>(drow) =
                    make_float2(acc[mf][nf][half * 2], acc[mf][nf][half * 2 + 1]);
            }
        }
    }
}

// ---------------------------------------------------------------------------
// Output projection: out[4096, 1024] = g_att @ Wo + bo.  grid (32, 16).
// ---------------------------------------------------------------------------
__global__ __launch_bounds__(256, 2) void proj_kernel(
    const float* __restrict__ Wo,
    const float* __restrict__ bo,
    float* __restrict__ out)
{
    extern __shared__ unsigned smw[];
    unsigned* As = smw;
    unsigned* Bs = smw + 2 * AS_WORDS;

    const int mt = blockIdx.x;                  // 0..31
    const int nt = blockIdx.y;                  // 0..15
    const float* A = g_att + (size_t)mt * 128 * DD;
    const float* Wn = Wo + nt * 64;

    const int tid  = threadIdx.x;
    const int lane = tid & 31;
    const int warp = tid >> 5;
    const int wm   = warp >> 1;
    const int wn   = warp & 1;
    const int lq   = lane >> 2;
    const int lr   = lane & 3;

    const int bl0_k = tid >> 4;
    const int bl0_n = (tid & 15) * 4;

    float acc[2][4][4];
#pragma unroll
    for (int mf = 0; mf < 2; mf++)
#pragma unroll
        for (int nf = 0; nf < 4; nf++)
#pragma unroll
            for (int j = 0; j < 4; j++) acc[mf][nf][j] = 0.f;

    float4 pa[4], pb[2];
    lda_regs(pa, A, DD, 0, tid);
    pb[0] = *reinterpret_cast<const float4*>(&Wn[(size_t)bl0_k * DD + bl0_n]);
    pb[1] = *reinterpret_cast<const float4*>(&Wn[(size_t)(bl0_k + 16) * DD + bl0_n]);
    sts_tiles(As, Bs, pa, pb, tid);
    __syncthreads();

    for (int k0 = 0; k0 < DD; k0 += 32) {
        const int buf = (k0 >> 5) & 1;
        const bool more = (k0 + 32) < DD;
        if (more) {
            lda_regs(pa, A, DD, k0 + 32, tid);
            pb[0] = *reinterpret_cast<const float4*>(&Wn[(size_t)(k0 + 32 + bl0_k) * DD + bl0_n]);
            pb[1] = *reinterpret_cast<const float4*>(&Wn[(size_t)(k0 + 48 + bl0_k) * DD + bl0_n]);
        }
        mma_block_step(As + buf * AS_WORDS, Bs + buf * BS_WORDS, acc, wm, wn, lq, lr);
        if (more)
            sts_tiles(As + (1 - buf) * AS_WORDS, Bs + (1 - buf) * BS_WORDS, pa, pb, tid);
        __syncthreads();
    }

#pragma unroll
    for (int mf = 0; mf < 2; mf++) {
#pragma unroll
        for (int nf = 0; nf < 4; nf++) {
            int row = wm * 32 + mf * 16 + lq;
            int col = nt * 64 + wn * 32 + nf * 8 + 2 * lr;
            float b0 = bo[col], b1 = bo[col + 1];
            float* C0 = out + (size_t)(mt * 128 + row) * DD + col;
            float* C1 = out + (size_t)(mt * 128 + row + 8) * DD + col;
            *reinterpret_cast<float2*>(C0) =
                make_float2(acc[mf][nf][0] + b0, acc[mf][nf][1] + b1);
            *reinterpret_cast<float2*>(C1) =
                make_float2(acc[mf][nf][2] + b0, acc[mf][nf][3] + b1);
        }
    }
}

// ---------------------------------------------------------------------------
// Causal flash attention, tf32 tensor cores (unchanged from R3).
// ---------------------------------------------------------------------------
#define ATTN_SMEM ((64*68 + 64*68 + 64*72 + 64*68) * 4)

__global__ void attn_kernel()
{
    extern __shared__ float sm[];
    float* Qs = sm;                 // [m][e] stride 68
    float* Ks = Qs + 64 * 68;       // [n][e] stride 68
    float* Vs = Ks + 64 * 68;       // [k][n] stride 72
    float* Ps = Vs + 64 * 72;       // [m][k] stride 68

    const int it = blockIdx.x;
    const int bh = blockIdx.y;
    const int b = bh >> 4, h = bh & 15;

    const float* Q  = g_q + (size_t)bh * TT * HSS + (size_t)it * 64 * HSS;
    const float* Kg = g_k + (size_t)bh * TT * HSS;
    const float* Vg = g_v + (size_t)bh * TT * HSS;

    const int tid  = threadIdx.x;
    const int lane = tid & 31;
    const int warp = tid >> 5;
    const int lq   = lane >> 2;
    const int lr   = lane & 3;
    const int mrow = warp * 16 + lq;

#pragma unroll
    for (int i = 0; i < 8; i++) {
        int l = tid + i * 128;
        int row = l >> 4;
        int c4  = l & 15;
        float4 v = *reinterpret_cast<const float4*>(&Q[(size_t)row * HSS + c4 * 4]);
        *reinterpret_cast<float4*>(&Qs[row * 68 + c4 * 4]) =
            make_float4(tf32r(v.x), tf32r(v.y), tf32r(v.z), tf32r(v.w));
    }

    float m0 = -1e30f, m1 = -1e30f, l0 = 0.f, l1 = 0.f;
    float o[8][4];
#pragma unroll
    for (int j = 0; j < 8; j++)
#pragma unroll
        for (int c = 0; c < 4; c++) o[j][c] = 0.f;

    const int ntiles = it + 1;
    for (int jt = 0; jt < ntiles; jt++) {
        __syncthreads();
        const float* Kt = Kg + (size_t)jt * 64 * HSS;
        const float* Vt = Vg + (size_t)jt * 64 * HSS;
#pragma unroll
        for (int i = 0; i < 8; i++) {
            int l = tid + i * 128;
            int row = l >> 4;
            int c4  = l & 15;
            float4 kv = *reinterpret_cast<const float4*>(&Kt[(size_t)row * HSS + c4 * 4]);
            *reinterpret_cast<float4*>(&Ks[row * 68 + c4 * 4]) =
                make_float4(tf32r(kv.x), tf32r(kv.y), tf32r(kv.z), tf32r(kv.w));
            float4 vv = *reinterpret_cast<const float4*>(&Vt[(size_t)row * HSS + c4 * 4]);
            *reinterpret_cast<float4*>(&Vs[row * 72 + c4 * 4]) =
                make_float4(tf32r(vv.x), tf32r(vv.y), tf32r(vv.z), tf32r(vv.w));
        }
        __syncthreads();

        float s[8][4];
#pragma unroll
        for (int j = 0; j < 8; j++)
#pragma unroll
            for (int c = 0; c < 4; c++) s[j][c] = 0.f;

#pragma unroll
        for (int ke = 0; ke < 8; ke++) {
            const int kc = ke * 8 + lr;
            unsigned a[4];
            a[0] = __float_as_uint(Qs[mrow * 68 + kc]);
            a[1] = __float_as_uint(Qs[(mrow + 8) * 68 + kc]);
            a[2] = __float_as_uint(Qs[mrow * 68 + kc + 4]);
            a[3] = __float_as_uint(Qs[(mrow + 8) * 68 + kc + 4]);
#pragma unroll
            for (int j = 0; j < 8; j++) {
                unsigned bfr[2];
                bfr[0] = __float_as_uint(Ks[(j * 8 + lq) * 68 + kc]);
                bfr[1] = __float_as_uint(Ks[(j * 8 + lq) * 68 + kc + 4]);
                mma8(s[j], a, bfr);
            }
        }

        const float scale = 0.125f;
#pragma unroll
        for (int j = 0; j < 8; j++)
#pragma unroll
            for (int c = 0; c < 4; c++) s[j][c] *= scale;

        if (jt == it) {
            int r0g = mrow, r1g = mrow + 8;
#pragma unroll
            for (int j = 0; j < 8; j++) {
                int c0 = j * 8 + 2 * lr, c1 = c0 + 1;
                if (c0 > r0g) s[j][0] = -1e30f;
                if (c1 > r0g) s[j][1] = -1e30f;
                if (c0 > r1g) s[j][2] = -1e30f;
                if (c1 > r1g) s[j][3] = -1e30f;
            }
        }

        float mx0 = -1e30f, mx1 = -1e30f;
#pragma unroll
        for (int j = 0; j < 8; j++) {
            mx0 = fmaxf(mx0, fmaxf(s[j][0], s[j][1]));
            mx1 = fmaxf(mx1, fmaxf(s[j][2], s[j][3]));
        }
        mx0 = fmaxf(mx0, __shfl_xor_sync(0xffffffffu, mx0, 1));
        mx0 = fmaxf(mx0, __shfl_xor_sync(0xffffffffu, mx0, 2));
        mx1 = fmaxf(mx1, __shfl_xor_sync(0xffffffffu, mx1, 1));
        mx1 = fmaxf(mx1, __shfl_xor_sync(0xffffffffu, mx1, 2));

        float mn0 = fmaxf(m0, mx0), mn1 = fmaxf(m1, mx1);
        float f0 = __expf(m0 - mn0), f1 = __expf(m1 - mn1);

        float rs0 = 0.f, rs1 = 0.f;
        float p[8][4];
#pragma unroll
        for (int j = 0; j < 8; j++) {
            p[j][0] = __expf(s[j][0] - mn0);
            p[j][1] = __expf(s[j][1] - mn0);
            p[j][2] = __expf(s[j][2] - mn1);
            p[j][3] = __expf(s[j][3] - mn1);
            rs0 += p[j][0] + p[j][1];
            rs1 += p[j][2] + p[j][3];
        }
        rs0 += __shfl_xor_sync(0xffffffffu, rs0, 1);
        rs0 += __shfl_xor_sync(0xffffffffu, rs0, 2);
        rs1 += __shfl_xor_sync(0xffffffffu, rs1, 1);
        rs1 += __shfl_xor_sync(0xffffffffu, rs1, 2);

        l0 = l0 * f0 + rs0;
        l1 = l1 * f1 + rs1;
        m0 = mn0; m1 = mn1;
#pragma unroll
        for (int j = 0; j < 8; j++) {
            o[j][0] *= f0; o[j][1] *= f0;
            o[j][2] *= f1; o[j][3] *= f1;
        }

#pragma unroll
        for (int j = 0; j < 8; j++) {
            int cb = j * 8 + 2 * lr;
            *reinterpret_cast<float2*>(&Ps[mrow * 68 + cb]) =
                make_float2(tf32r(p[j][0]), tf32r(p[j][1]));
            *reinterpret_cast<float2*>(&Ps[(mrow + 8) * 68 + cb]) =
                make_float2(tf32r(p[j][2]), tf32r(p[j][3]));
        }
        __syncwarp();

#pragma unroll
        for (int kk = 0; kk < 8; kk++) {
            const int kc = kk * 8 + lr;
            unsigned a[4];
            a[0] = __float_as_uint(Ps[mrow * 68 + kc]);
            a[1] = __float_as_uint(Ps[(mrow + 8) * 68 + kc]);
            a[2] = __float_as_uint(Ps[mrow * 68 + kc + 4]);
            a[3] = __float_as_uint(Ps[(mrow + 8) * 68 + kc + 4]);
#pragma unroll
            for (int j = 0; j < 8; j++) {
                unsigned bfr[2];
                bfr[0] = __float_as_uint(Vs[kc * 72 + j * 8 + lq]);
                bfr[1] = __float_as_uint(Vs[(kc + 4) * 72 + j * 8 + lq]);
                mma8(o[j], a, bfr);
            }
        }
    }

    float inv0 = 1.f / l0, inv1 = 1.f / l1;
    size_t row0 = (size_t)b * TT + (size_t)it * 64 + mrow;
    size_t row1 = row0 + 8;
#pragma unroll
    for (int j = 0; j < 8; j++) {
        int cb = h * HSS + j * 8 + 2 * lr;
        *reinterpret_cast<float2*>(&g_att[row0 * DD + cb]) =
            make_float2(o[j][0] * inv0, o[j][1] * inv0);
        *reinterpret_cast<float2*>(&g_att[row1 * DD + cb]) =
            make_float2(o[j][2] * inv1, o[j][3] * inv1);
    }
}

extern "C" void kernel_launch(void* const* d_in, const int* in_sizes, int n_in,
                              void* d_out, int out_size)
{
    const float* x  = (const float*)d_in[0];
    const float* Wq = (const float*)d_in[1];
    const float* Wk = (const float*)d_in[2];
    const float* Wv = (const float*)d_in[3];
    const float* Wo = (const float*)d_in[4];
    const float* bo = (const float*)d_in[5];
    float* out = (float*)d_out;

    cudaFuncSetAttribute(qkv_kernel,
                         cudaFuncAttributeMaxDynamicSharedMemorySize, GEMM_SMEM);
    cudaFuncSetAttribute(proj_kernel,
                         cudaFuncAttributeMaxDynamicSharedMemorySize, GEMM_SMEM);
    cudaFuncSetAttribute(attn_kernel,
                         cudaFuncAttributeMaxDynamicSharedMemorySize, ATTN_SMEM);

    dim3 g1((BB * TT) / 128, 48);
    qkv_kernel<<<g1, 256, GEMM_SMEM>>>(x, Wq, Wk, Wv);

    dim3 g2(TT / 64, BB * HH);
    attn_kernel<<<g2, 128, ATTN_SMEM>>>();

    dim3 g3((BB * TT) / 128, DD / 64);
    proj_kernel<<<g3, 256, GEMM_SMEM>>>(Wo, bo, out);
}

// round 7
// speedup vs baseline: 1.8150x; 1.8150x over previous
#include <cuda_runtime.h>
#include <cuda_fp16.h>
#include <math.h>
#include <cstdint>

#define BB 4
#define TT 1024
#define DD 1024
#define HH 16
#define HSS 64

// Scratch (no cudaMalloc allowed)
__device__ __align__(16) __half g_xh[BB*TT*DD];            // x in fp16
__device__ __align__(16) unsigned g_wp[3*HH*512*HSS];      // W q/k/v paired: [which][h][kp][hs]
__device__ __align__(16) unsigned g_wop[512*DD];           // Wo paired: [kp][n]
__device__ __align__(16) __half g_q[BB*HH*TT*HSS];
__device__ __align__(16) __half g_k[BB*HH*TT*HSS];
__device__ __align__(16) __half g_v[BB*HH*TT*HSS];
__device__ __align__(16) __half g_att[BB*TT*DD];

// ---------------------------------------------------------------------------
// fp16 m16n8k16 mma (fp32 accumulate)
// ---------------------------------------------------------------------------
__device__ __forceinline__ void mma16h(float* d, const unsigned* a, const unsigned* b) {
    asm volatile(
        "mma.sync.aligned.m16n8k16.row.col.f32.f16.f16.f32 "
        "{%0,%1,%2,%3}, {%4,%5,%6,%7}, {%8,%9}, {%0,%1,%2,%3};"
        : "+f"(d[0]), "+f"(d[1]), "+f"(d[2]), "+f"(d[3])
        : "r"(a[0]), "r"(a[1]), "r"(a[2]), "r"(a[3]),
          "r"(b[0]), "r"(b[1]));
}

__device__ __forceinline__ unsigned packh2(float a, float b) {
    __half2 h = __floats2half2_rn(a, b);
    return *reinterpret_cast<unsigned*>(&h);
}

// ---------------------------------------------------------------------------
// Convert/pack kernel: x -> fp16; Wq/Wk/Wv -> paired fp16 words [which][h][kp][hs];
// Wo -> paired words [kp][n].
// ---------------------------------------------------------------------------
__global__ void conv_kernel(const float* __restrict__ x,
                            const float* __restrict__ Wq,
                            const float* __restrict__ Wk,
                            const float* __restrict__ Wv,
                            const float* __restrict__ Wo)
{
    const int stride = gridDim.x * blockDim.x;
    const int tid0 = blockIdx.x * blockDim.x + threadIdx.x;

    const int XN = BB * TT * DD;              // 4194304
    for (int i = tid0; i < XN; i += stride)
        g_xh[i] = __float2half_rn(x[i]);

    const int WPN = 3 * HH * 512 * HSS;       // 1572864
    for (int i = tid0; i < WPN; i += stride) {
        int hs = i & 63;
        int kp = (i >> 6) & 511;
        int h  = (i >> 15) & 15;
        int which = i >> 19;
        const float* W = (which == 0 ? Wq : which == 1 ? Wk : Wv);
        const float* src = W + ((size_t)h * DD + 2 * kp) * HSS + hs;
        g_wp[i] = packh2(src[0], src[HSS]);
    }

    const int WON = 512 * DD;                 // 524288
    for (int i = tid0; i < WON; i += stride) {
        int n = i & 1023;
        int kp = i >> 10;
        g_wop[i] = packh2(Wo[(size_t)(2 * kp) * DD + n],
                          Wo[(size_t)(2 * kp + 1) * DD + n]);
    }
}

// ---------------------------------------------------------------------------
// fp16 GEMM machinery: block 128x128, 8 warps = 2(m) x 4(n), warp 64x32, BK=32.
// Aw[row 128][kp 16 + pad4]   banks (20*row + kp) -> conflict-free frags
// Bw[kp 16][n 128 + pad8]     banks (8*kp + n)    -> conflict-free frags
// ---------------------------------------------------------------------------
#define AW_STRIDE 20
#define BW_STRIDE 136

__device__ __forceinline__ void gemm_mma_chunk(
    const unsigned* __restrict__ Aw, const unsigned* __restrict__ Bw,
    float acc[4][4][4], int wm, int wn, int lq, int lr)
{
#pragma unroll
    for (int kc = 0; kc < 2; kc++) {
        const int kb = kc * 8 + lr;
        unsigned a[4][4];
#pragma unroll
        for (int mf = 0; mf < 4; mf++) {
            int mr = wm * 64 + mf * 16 + lq;
            a[mf][0] = Aw[mr * AW_STRIDE + kb];
            a[mf][1] = Aw[(mr + 8) * AW_STRIDE + kb];
            a[mf][2] = Aw[mr * AW_STRIDE + kb + 4];
            a[mf][3] = Aw[(mr + 8) * AW_STRIDE + kb + 4];
        }
        unsigned b[4][2];
#pragma unroll
        for (int nf = 0; nf < 4; nf++) {
            int nc = wn * 32 + nf * 8 + lq;
            b[nf][0] = Bw[kb * BW_STRIDE + nc];
            b[nf][1] = Bw[(kb + 4) * BW_STRIDE + nc];
        }
#pragma unroll
        for (int mf = 0; mf < 4; mf++)
#pragma unroll
            for (int nf = 0; nf < 4; nf++)
                mma16h(acc[mf][nf], a[mf], b[nf]);
    }
}

// ---------------------------------------------------------------------------
// QKV: logical GEMM [4096 x 3072 x 1024]. grid (32, 24); nt>>3 = Q/K/V,
// (nt&7)*2 = first of 2 heads in this 128-wide n-tile.
// ---------------------------------------------------------------------------
__global__ __launch_bounds__(256, 2) void qkv_kernel()
{
    __shared__ unsigned Aw[128 * AW_STRIDE];
    __shared__ unsigned Bw[16 * BW_STRIDE];

    const int mt = blockIdx.x;
    const int nt = blockIdx.y;
    const int which = nt >> 3;
    const int h0 = (nt & 7) * 2;

    __half* dst = (which == 0 ? g_q : which == 1 ? g_k : g_v);
    const unsigned* Wp = g_wp + (size_t)which * HH * 512 * HSS;

    const int tid  = threadIdx.x;
    const int lane = tid & 31;
    const int warp = tid >> 5;
    const int wm   = warp >> 2;
    const int wn   = warp & 3;
    const int lq   = lane >> 2;
    const int lr   = lane & 3;

    float acc[4][4][4];
#pragma unroll
    for (int mf = 0; mf < 4; mf++)
#pragma unroll
        for (int nf = 0; nf < 4; nf++)
#pragma unroll
            for (int j = 0; j < 4; j++) acc[mf][nf][j] = 0.f;

    for (int k0 = 0; k0 < DD; k0 += 32) {
        // A tile: 512 uint4 units (row, q4)
#pragma unroll
        for (int i = 0; i < 2; i++) {
            int u = tid + i * 256;
            int row = u >> 2;
            int q4  = u & 3;
            uint4 v = *reinterpret_cast<const uint4*>(
                &g_xh[(size_t)(mt * 128 + row) * DD + k0 + q4 * 8]);
            *reinterpret_cast<uint4*>(&Aw[row * AW_STRIDE + q4 * 4]) = v;
        }
        // B tile: 512 uint4 units (kp, n4)
#pragma unroll
        for (int i = 0; i < 2; i++) {
            int u = tid + i * 256;
            int kp = u >> 5;
            int n  = (u & 31) * 4;
            int h  = h0 + (n >> 6);
            int hs = n & 63;
            uint4 v = *reinterpret_cast<const uint4*>(
                &Wp[((size_t)h * 512 + (k0 >> 1) + kp) * HSS + hs]);
            *reinterpret_cast<uint4*>(&Bw[kp * BW_STRIDE + n]) = v;
        }
        __syncthreads();
        gemm_mma_chunk(Aw, Bw, acc, wm, wn, lq, lr);
        __syncthreads();
    }

    // Epilogue -> fp16 scratch [bh][t][hs]
#pragma unroll
    for (int mf = 0; mf < 4; mf++) {
#pragma unroll
        for (int nf = 0; nf < 4; nf++) {
            int row = wm * 64 + mf * 16 + lq;
            int col = wn * 32 + nf * 8 + 2 * lr;
            int h   = h0 + (col >> 6);
            int hs  = col & 63;
#pragma unroll
            for (int half = 0; half < 2; half++) {
                int gr = mt * 128 + row + half * 8;
                int b = gr >> 10, t = gr & 1023;
                __half2* dp = reinterpret_cast<__half2*>(
                    dst + ((size_t)(b * HH + h) * TT + t) * HSS + hs);
                *dp = __floats2half2_rn(acc[mf][nf][half * 2],
                                        acc[mf][nf][half * 2 + 1]);
            }
        }
    }
}

// ---------------------------------------------------------------------------
// Output projection: out[4096,1024] = g_att @ Wo + bo.  grid (32, 8).
// ---------------------------------------------------------------------------
__global__ __launch_bounds__(256, 2) void proj_kernel(
    const float* __restrict__ bo, float* __restrict__ out)
{
    __shared__ unsigned Aw[128 * AW_STRIDE];
    __shared__ unsigned Bw[16 * BW_STRIDE];

    const int mt = blockIdx.x;
    const int nt = blockIdx.y;

    const int tid  = threadIdx.x;
    const int lane = tid & 31;
    const int warp = tid >> 5;
    const int wm   = warp >> 2;
    const int wn   = warp & 3;
    const int lq   = lane >> 2;
    const int lr   = lane & 3;

    float acc[4][4][4];
#pragma unroll
    for (int mf = 0; mf < 4; mf++)
#pragma unroll
        for (int nf = 0; nf < 4; nf++)
#pragma unroll
            for (int j = 0; j < 4; j++) acc[mf][nf][j] = 0.f;

    for (int k0 = 0; k0 < DD; k0 += 32) {
#pragma unroll
        for (int i = 0; i < 2; i++) {
            int u = tid + i * 256;
            int row = u >> 2;
            int q4  = u & 3;
            uint4 v = *reinterpret_cast<const uint4*>(
                &g_att[(size_t)(mt * 128 + row) * DD + k0 + q4 * 8]);
            *reinterpret_cast<uint4*>(&Aw[row * AW_STRIDE + q4 * 4]) = v;
        }
#pragma unroll
        for (int i = 0; i < 2; i++) {
            int u = tid + i * 256;
            int kp = u >> 5;
            int n  = (u & 31) * 4;
            uint4 v = *reinterpret_cast<const uint4*>(
                &g_wop[((size_t)(k0 >> 1) + kp) * DD + nt * 128 + n]);
            *reinterpret_cast<uint4*>(&Bw[kp * BW_STRIDE + n]) = v;
        }
        __syncthreads();
        gemm_mma_chunk(Aw, Bw, acc, wm, wn, lq, lr);
        __syncthreads();
    }

#pragma unroll
    for (int mf = 0; mf < 4; mf++) {
#pragma unroll
        for (int nf = 0; nf < 4; nf++) {
            int row = wm * 64 + mf * 16 + lq;
            int col = nt * 128 + wn * 32 + nf * 8 + 2 * lr;
            float b0 = bo[col], b1 = bo[col + 1];
            float* C0 = out + (size_t)(mt * 128 + row) * DD + col;
            float* C1 = out + (size_t)(mt * 128 + row + 8) * DD + col;
            *reinterpret_cast<float2*>(C0) =
                make_float2(acc[mf][nf][0] + b0, acc[mf][nf][1] + b1);
            *reinterpret_cast<float2*>(C1) =
                make_float2(acc[mf][nf][2] + b0, acc[mf][nf][3] + b1);
        }
    }
}

// ---------------------------------------------------------------------------
// Causal flash attention, fp16 m16n8k16. Block = 128 threads (4 warps),
// q-tile 64; warp w owns rows [16w, 16w+16). P feeds PV directly from regs.
// Qs/Ks: [row 64][kp 32 + pad4] packed fp16-pair words.
// Vs:    [kp 32][n 64 + pad8]   words = (V[2kp][n], V[2kp+1][n]).
// ---------------------------------------------------------------------------
__global__ void attn_kernel()
{
    __shared__ unsigned Qs[64 * 36];
    __shared__ unsigned Ks[64 * 36];
    __shared__ unsigned Vs[32 * 72];

    const int it = blockIdx.x;
    const int bh = blockIdx.y;
    const int b = bh >> 4, h = bh & 15;

    const __half* Q  = g_q + (size_t)bh * TT * HSS + (size_t)it * 64 * HSS;
    const __half* Kg = g_k + (size_t)bh * TT * HSS;
    const __half* Vg = g_v + (size_t)bh * TT * HSS;

    const int tid  = threadIdx.x;
    const int lane = tid & 31;
    const int warp = tid >> 5;
    const int lq   = lane >> 2;
    const int lr   = lane & 3;
    const int mrow = warp * 16 + lq;

    // Load Q: 512 uint4 units (row, u)
#pragma unroll
    for (int i = 0; i < 4; i++) {
        int l = tid + i * 128;
        int row = l >> 3;
        int u   = l & 7;
        uint4 v = *reinterpret_cast<const uint4*>(&Q[(size_t)row * HSS + u * 8]);
        *reinterpret_cast<uint4*>(&Qs[row * 36 + u * 4]) = v;
    }

    float m0 = -1e30f, m1 = -1e30f, l0 = 0.f, l1 = 0.f;
    float o[8][4];
#pragma unroll
    for (int j = 0; j < 8; j++)
#pragma unroll
        for (int c = 0; c < 4; c++) o[j][c] = 0.f;

    const int ntiles = it + 1;
    for (int jt = 0; jt < ntiles; jt++) {
        __syncthreads();   // prior-iter reads done (also covers Q store on jt==0)
        const __half* Kt = Kg + (size_t)jt * 64 * HSS;
        const __half* Vt = Vg + (size_t)jt * 64 * HSS;
#pragma unroll
        for (int i = 0; i < 4; i++) {
            int l = tid + i * 128;
            int row = l >> 3;
            int u   = l & 7;
            uint4 v = *reinterpret_cast<const uint4*>(&Kt[(size_t)row * HSS + u * 8]);
            *reinterpret_cast<uint4*>(&Ks[row * 36 + u * 4]) = v;
        }
        // V: interleave token pairs. 256 units (kp, n-oct) over 2 iters.
#pragma unroll
        for (int i = 0; i < 2; i++) {
            int l = tid + i * 128;
            int kp = l >> 3;
            int no = l & 7;
            uint4 r0 = *reinterpret_cast<const uint4*>(&Vt[(size_t)(2 * kp) * HSS + no * 8]);
            uint4 r1 = *reinterpret_cast<const uint4*>(&Vt[(size_t)(2 * kp + 1) * HSS + no * 8]);
            uint4 w0, w1;
            w0.x = __byte_perm(r0.x, r1.x, 0x5410);
            w0.y = __byte_perm(r0.x, r1.x, 0x7632);
            w0.z = __byte_perm(r0.y, r1.y, 0x5410);
            w0.w = __byte_perm(r0.y, r1.y, 0x7632);
            w1.x = __byte_perm(r0.z, r1.z, 0x5410);
            w1.y = __byte_perm(r0.z, r1.z, 0x7632);
            w1.z = __byte_perm(r0.w, r1.w, 0x5410);
            w1.w = __byte_perm(r0.w, r1.w, 0x7632);
            *reinterpret_cast<uint4*>(&Vs[kp * 72 + no * 8])     = w0;
            *reinterpret_cast<uint4*>(&Vs[kp * 72 + no * 8 + 4]) = w1;
        }
        __syncthreads();

        // ---- S = Q K^T (fp16 k16, 32 mmas)
        float s[8][4];
#pragma unroll
        for (int j = 0; j < 8; j++)
#pragma unroll
            for (int c = 0; c < 4; c++) s[j][c] = 0.f;

#pragma unroll
        for (int c = 0; c < 4; c++) {
            const int kb = c * 8 + lr;
            unsigned a[4];
            a[0] = Qs[mrow * 36 + kb];
            a[1] = Qs[(mrow + 8) * 36 + kb];
            a[2] = Qs[mrow * 36 + kb + 4];
            a[3] = Qs[(mrow + 8) * 36 + kb + 4];
#pragma unroll
            for (int j = 0; j < 8; j++) {
                unsigned bb[2];
                bb[0] = Ks[(j * 8 + lq) * 36 + kb];
                bb[1] = Ks[(j * 8 + lq) * 36 + kb + 4];
                mma16h(s[j], a, bb);
            }
        }

        const float scale = 0.125f;
#pragma unroll
        for (int j = 0; j < 8; j++)
#pragma unroll
            for (int c = 0; c < 4; c++) s[j][c] *= scale;

        if (jt == it) {  // causal mask on diagonal tile
            int r0g = mrow, r1g = mrow + 8;
#pragma unroll
            for (int j = 0; j < 8; j++) {
                int c0 = j * 8 + 2 * lr, c1 = c0 + 1;
                if (c0 > r0g) s[j][0] = -1e30f;
                if (c1 > r0g) s[j][1] = -1e30f;
                if (c0 > r1g) s[j][2] = -1e30f;
                if (c1 > r1g) s[j][3] = -1e30f;
            }
        }

        // ---- online softmax (p overwrites s)
        float mx0 = -1e30f, mx1 = -1e30f;
#pragma unroll
        for (int j = 0; j < 8; j++) {
            mx0 = fmaxf(mx0, fmaxf(s[j][0], s[j][1]));
            mx1 = fmaxf(mx1, fmaxf(s[j][2], s[j][3]));
        }
        mx0 = fmaxf(mx0, __shfl_xor_sync(0xffffffffu, mx0, 1));
        mx0 = fmaxf(mx0, __shfl_xor_sync(0xffffffffu, mx0, 2));
        mx1 = fmaxf(mx1, __shfl_xor_sync(0xffffffffu, mx1, 1));
        mx1 = fmaxf(mx1, __shfl_xor_sync(0xffffffffu, mx1, 2));

        float mn0 = fmaxf(m0, mx0), mn1 = fmaxf(m1, mx1);
        float f0 = __expf(m0 - mn0), f1 = __expf(m1 - mn1);

        float rs0 = 0.f, rs1 = 0.f;
#pragma unroll
        for (int j = 0; j < 8; j++) {
            s[j][0] = __expf(s[j][0] - mn0);
            s[j][1] = __expf(s[j][1] - mn0);
            s[j][2] = __expf(s[j][2] - mn1);
            s[j][3] = __expf(s[j][3] - mn1);
            rs0 += s[j][0] + s[j][1];
            rs1 += s[j][2] + s[j][3];
        }
        rs0 += __shfl_xor_sync(0xffffffffu, rs0, 1);
        rs0 += __shfl_xor_sync(0xffffffffu, rs0, 2);
        rs1 += __shfl_xor_sync(0xffffffffu, rs1, 1);
        rs1 += __shfl_xor_sync(0xffffffffu, rs1, 2);

        l0 = l0 * f0 + rs0;
        l1 = l1 * f1 + rs1;
        m0 = mn0; m1 = mn1;
#pragma unroll
        for (int j = 0; j < 8; j++) {
            o[j][0] *= f0; o[j][1] *= f0;
            o[j][2] *= f1; o[j][3] *= f1;
        }

        // ---- O += P V  (P packed from registers, 32 mmas)
#pragma unroll
        for (int c = 0; c < 4; c++) {
            unsigned a[4];
            a[0] = packh2(s[2 * c][0],     s[2 * c][1]);
            a[1] = packh2(s[2 * c][2],     s[2 * c][3]);
            a[2] = packh2(s[2 * c + 1][0], s[2 * c + 1][1]);
            a[3] = packh2(s[2 * c + 1][2], s[2 * c + 1][3]);
            const int kb = c * 8 + lr;
#pragma unroll
            for (int j = 0; j < 8; j++) {
                unsigned bb[2];
                bb[0] = Vs[kb * 72 + j * 8 + lq];
                bb[1] = Vs[(kb + 4) * 72 + j * 8 + lq];
                mma16h(o[j], a, bb);
            }
        }
    }

    // normalize + write fp16 concat-head layout
    float inv0 = 1.f / l0, inv1 = 1.f / l1;
    size_t row0 = (size_t)b * TT + (size_t)it * 64 + mrow;
    size_t row1 = row0 + 8;
#pragma unroll
    for (int j = 0; j < 8; j++) {
        int cb = h * HSS + j * 8 + 2 * lr;
        *reinterpret_cast<__half2*>(&g_att[row0 * DD + cb]) =
            __floats2half2_rn(o[j][0] * inv0, o[j][1] * inv0);
        *reinterpret_cast<__half2*>(&g_att[row1 * DD + cb]) =
            __floats2half2_rn(o[j][2] * inv1, o[j][3] * inv1);
    }
}

extern "C" void kernel_launch(void* const* d_in, const int* in_sizes, int n_in,
                              void* d_out, int out_size)
{
    const float* x  = (const float*)d_in[0];
    const float* Wq = (const float*)d_in[1];
    const float* Wk = (const float*)d_in[2];
    const float* Wv = (const float*)d_in[3];
    const float* Wo = (const float*)d_in[4];
    const float* bo = (const float*)d_in[5];
    float* out = (float*)d_out;

    conv_kernel<<<512, 256>>>(x, Wq, Wk, Wv, Wo);

    dim3 g1((BB * TT) / 128, 24);
    qkv_kernel<<<g1, 256>>>();

    dim3 g2(TT / 64, BB * HH);
    attn_kernel<<<g2, 128>>>();

    dim3 g3((BB * TT) / 128, DD / 128);
    proj_kernel<<<g3, 256>>>(bo, out);
}

// round 8
// speedup vs baseline: 2.0892x; 1.1511x over previous
#include <cuda_runtime.h>
#include <cuda_fp16.h>
#include <math.h>
#include <cstdint>

#define BB 4
#define TT 1024
#define DD 1024
#define HH 16
#define HSS 64

// Scratch (no cudaMalloc allowed)
__device__ __align__(16) __half g_xh[BB*TT*DD];            // x in fp16
__device__ __align__(16) unsigned g_wp[3*HH*512*HSS];      // W q/k/v paired: [which][h][kp][hs]
__device__ __align__(16) unsigned g_wop[512*DD];           // Wo paired: [kp][n]
__device__ __align__(16) __half g_q[BB*HH*TT*HSS];
__device__ __align__(16) __half g_k[BB*HH*TT*HSS];
__device__ __align__(16) __half g_v[BB*HH*TT*HSS];
__device__ __align__(16) __half g_att[BB*TT*DD];

// ---------------------------------------------------------------------------
// helpers
// ---------------------------------------------------------------------------
__device__ __forceinline__ void mma16h(float* d, const unsigned* a, const unsigned* b) {
    asm volatile(
        "mma.sync.aligned.m16n8k16.row.col.f32.f16.f16.f32 "
        "{%0,%1,%2,%3}, {%4,%5,%6,%7}, {%8,%9}, {%0,%1,%2,%3};"
        : "+f"(d[0]), "+f"(d[1]), "+f"(d[2]), "+f"(d[3])
        : "r"(a[0]), "r"(a[1]), "r"(a[2]), "r"(a[3]),
          "r"(b[0]), "r"(b[1]));
}

__device__ __forceinline__ unsigned packh2(float a, float b) {
    __half2 h = __floats2half2_rn(a, b);
    return *reinterpret_cast<unsigned*>(&h);
}

__device__ __forceinline__ uint32_t smem_u32(const void* p) {
    uint32_t a;
    asm("{ .reg .u64 t; cvta.to.shared.u64 t, %1; cvt.u32.u64 %0, t; }"
        : "=r"(a) : "l"(p));
    return a;
}

__device__ __forceinline__ void cp16(uint32_t s, const void* g) {
    asm volatile("cp.async.cg.shared.global [%0], [%1], 16;"
                 :: "r"(s), "l"(g) : "memory");
}
#define CP_COMMIT() asm volatile("cp.async.commit_group;" ::: "memory")
#define CP_WAIT1()  asm volatile("cp.async.wait_group 1;" ::: "memory")
#define CP_WAIT0()  asm volatile("cp.async.wait_group 0;" ::: "memory")

// ---------------------------------------------------------------------------
// Convert/pack kernel (vectorized): x -> fp16; Wq/Wk/Wv -> paired fp16 words
// [which][h][kp][hs]; Wo -> paired words [kp][n].
// ---------------------------------------------------------------------------
__global__ void conv_kernel(const float* __restrict__ x,
                            const float* __restrict__ Wq,
                            const float* __restrict__ Wk,
                            const float* __restrict__ Wv,
                            const float* __restrict__ Wo)
{
    const int stride = gridDim.x * blockDim.x;
    const int tid0 = blockIdx.x * blockDim.x + threadIdx.x;

    const int XN4 = (BB * TT * DD) / 4;        // 1048576
    for (int i = tid0; i < XN4; i += stride) {
        float4 v = reinterpret_cast<const float4*>(x)[i];
        uint2 o;
        o.x = packh2(v.x, v.y);
        o.y = packh2(v.z, v.w);
        reinterpret_cast<uint2*>(g_xh)[i] = o;
    }

    const int WP4 = (3 * HH * 512 * HSS) / 4;  // 393216
    for (int i = tid0; i < WP4; i += stride) {
        int w0 = i * 4;
        int hs = w0 & 63;
        int kp = (w0 >> 6) & 511;
        int h  = (w0 >> 15) & 15;
        int which = w0 >> 19;
        const float* W = (which == 0 ? Wq : which == 1 ? Wk : Wv);
        const float* s0 = W + ((size_t)h * DD + 2 * kp) * HSS + hs;
        float4 a = *reinterpret_cast<const float4*>(s0);
        float4 b = *reinterpret_cast<const float4*>(s0 + HSS);
        uint4 o;
        o.x = packh2(a.x, b.x); o.y = packh2(a.y, b.y);
        o.z = packh2(a.z, b.z); o.w = packh2(a.w, b.w);
        reinterpret_cast<uint4*>(g_wp)[i] = o;
    }

    const int WO4 = (512 * DD) / 4;            // 131072
    for (int i = tid0; i < WO4; i += stride) {
        int w0 = i * 4;
        int n  = w0 & 1023;
        int kp = w0 >> 10;
        const float* s0 = Wo + (size_t)(2 * kp) * DD + n;
        float4 a = *reinterpret_cast<const float4*>(s0);
        float4 b = *reinterpret_cast<const float4*>(s0 + DD);
        uint4 o;
        o.x = packh2(a.x, b.x); o.y = packh2(a.y, b.y);
        o.z = packh2(a.z, b.z); o.w = packh2(a.w, b.w);
        reinterpret_cast<uint4*>(g_wop)[i] = o;
    }
}

// ---------------------------------------------------------------------------
// fp16 GEMM machinery: block 128x128, 8 warps = 2(m) x 4(n), warp 64x32, BK=32.
// Aw[row 128][kp 16 + pad4]   banks (20*row + kp) -> conflict-free frags
// Bw[kp 16][n 128 + pad8]     banks (8*kp + n)    -> conflict-free frags
// 3-stage cp.async pipeline.
// ---------------------------------------------------------------------------
#define AW_STRIDE 20
#define BW_STRIDE 136
#define AW_WORDS  (128 * AW_STRIDE)     // 2560
#define BW_WORDS  (16 * BW_STRIDE)      // 2176
#define NSTAGE 3
#define PIPE_SMEM ((AW_WORDS + BW_WORDS) * NSTAGE * 4)   // 56832 bytes

__device__ __forceinline__ void gemm_mma_chunk(
    const unsigned* __restrict__ Aw, const unsigned* __restrict__ Bw,
    float acc[4][4][4], int wm, int wn, int lq, int lr)
{
#pragma unroll
    for (int kc = 0; kc < 2; kc++) {
        const int kb = kc * 8 + lr;
        unsigned a[4][4];
#pragma unroll
        for (int mf = 0; mf < 4; mf++) {
            int mr = wm * 64 + mf * 16 + lq;
            a[mf][0] = Aw[mr * AW_STRIDE + kb];
            a[mf][1] = Aw[(mr + 8) * AW_STRIDE + kb];
            a[mf][2] = Aw[mr * AW_STRIDE + kb + 4];
            a[mf][3] = Aw[(mr + 8) * AW_STRIDE + kb + 4];
        }
        unsigned b[4][2];
#pragma unroll
        for (int nf = 0; nf < 4; nf++) {
            int nc = wn * 32 + nf * 8 + lq;
            b[nf][0] = Bw[kb * BW_STRIDE + nc];
            b[nf][1] = Bw[(kb + 4) * BW_STRIDE + nc];
        }
#pragma unroll
        for (int mf = 0; mf < 4; mf++)
#pragma unroll
            for (int nf = 0; nf < 4; nf++)
                mma16h(acc[mf][nf], a[mf], b[nf]);
    }
}

// ---------------------------------------------------------------------------
// QKV: logical GEMM [4096 x 3072 x 1024]. grid (32, 24); nt>>3 = Q/K/V,
// (nt&7)*2 = first of 2 heads in this 128-wide n-tile.
// ---------------------------------------------------------------------------
__device__ __forceinline__ void qkv_issue(
    uint32_t a_s, uint32_t b_s, int mt, const unsigned* Wp, int h0, int k0, int tid)
{
#pragma unroll
    for (int i = 0; i < 2; i++) {
        int u = tid + i * 256;
        int row = u >> 2;
        int q4  = u & 3;
        cp16(a_s + (row * AW_STRIDE + q4 * 4) * 4,
             &g_xh[(size_t)(mt * 128 + row) * DD + k0 + q4 * 8]);
    }
#pragma unroll
    for (int i = 0; i < 2; i++) {
        int u = tid + i * 256;
        int kp = u >> 5;
        int n  = (u & 31) * 4;
        int h  = h0 + (n >> 6);
        int hs = n & 63;
        cp16(b_s + (kp * BW_STRIDE + n) * 4,
             &Wp[((size_t)h * 512 + (k0 >> 1) + kp) * HSS + hs]);
    }
}

__global__ __launch_bounds__(256, 2) void qkv_kernel()
{
    extern __shared__ unsigned dsm[];
    unsigned* AwB = dsm;                       // [NSTAGE][AW_WORDS]
    unsigned* BwB = dsm + NSTAGE * AW_WORDS;   // [NSTAGE][BW_WORDS]
    const uint32_t a_base = smem_u32(AwB);
    const uint32_t b_base = smem_u32(BwB);

    const int mt = blockIdx.x;
    const int nt = blockIdx.y;
    const int which = nt >> 3;
    const int h0 = (nt & 7) * 2;

    __half* dst = (which == 0 ? g_q : which == 1 ? g_k : g_v);
    const unsigned* Wp = g_wp + (size_t)which * HH * 512 * HSS;

    const int tid  = threadIdx.x;
    const int lane = tid & 31;
    const int warp = tid >> 5;
    const int wm   = warp >> 2;
    const int wn   = warp & 3;
    const int lq   = lane >> 2;
    const int lr   = lane & 3;

    float acc[4][4][4];
#pragma unroll
    for (int mf = 0; mf < 4; mf++)
#pragma unroll
        for (int nf = 0; nf < 4; nf++)
#pragma unroll
            for (int j = 0; j < 4; j++) acc[mf][nf][j] = 0.f;

    // prologue: chunks 0,1
    qkv_issue(a_base, b_base, mt, Wp, h0, 0, tid);
    CP_COMMIT();
    qkv_issue(a_base + AW_WORDS * 4, b_base + BW_WORDS * 4, mt, Wp, h0, 32, tid);
    CP_COMMIT();

    for (int ci = 0; ci < 32; ci++) {
        if (ci < 30) CP_WAIT1(); else CP_WAIT0();
        __syncthreads();   // chunk ci visible; all warps done with chunk ci-1
        if (ci + 2 < 32) {
            int s = (ci + 2) % NSTAGE;
            qkv_issue(a_base + s * AW_WORDS * 4, b_base + s * BW_WORDS * 4,
                      mt, Wp, h0, (ci + 2) * 32, tid);
            CP_COMMIT();
        }
        int s = ci % NSTAGE;
        gemm_mma_chunk(AwB + s * AW_WORDS, BwB + s * BW_WORDS, acc, wm, wn, lq, lr);
    }

    // Epilogue -> fp16 scratch [bh][t][hs]
#pragma unroll
    for (int mf = 0; mf < 4; mf++) {
#pragma unroll
        for (int nf = 0; nf < 4; nf++) {
            int row = wm * 64 + mf * 16 + lq;
            int col = wn * 32 + nf * 8 + 2 * lr;
            int h   = h0 + (col >> 6);
            int hs  = col & 63;
#pragma unroll
            for (int half = 0; half < 2; half++) {
                int gr = mt * 128 + row + half * 8;
                int b = gr >> 10, t = gr & 1023;
                __half2* dp = reinterpret_cast<__half2*>(
                    dst + ((size_t)(b * HH + h) * TT + t) * HSS + hs);
                *dp = __floats2half2_rn(acc[mf][nf][half * 2],
                                        acc[mf][nf][half * 2 + 1]);
            }
        }
    }
}

// ---------------------------------------------------------------------------
// Output projection: out[4096,1024] = g_att @ Wo + bo.  grid (32, 8).
// ---------------------------------------------------------------------------
__device__ __forceinline__ void proj_issue(
    uint32_t a_s, uint32_t b_s, int mt, int nt, int k0, int tid)
{
#pragma unroll
    for (int i = 0; i < 2; i++) {
        int u = tid + i * 256;
        int row = u >> 2;
        int q4  = u & 3;
        cp16(a_s + (row * AW_STRIDE + q4 * 4) * 4,
             &g_att[(size_t)(mt * 128 + row) * DD + k0 + q4 * 8]);
    }
#pragma unroll
    for (int i = 0; i < 2; i++) {
        int u = tid + i * 256;
        int kp = u >> 5;
        int n  = (u & 31) * 4;
        cp16(b_s + (kp * BW_STRIDE + n) * 4,
             &g_wop[((size_t)(k0 >> 1) + kp) * DD + nt * 128 + n]);
    }
}

__global__ __launch_bounds__(256, 2) void proj_kernel(
    const float* __restrict__ bo, float* __restrict__ out)
{
    extern __shared__ unsigned dsm[];
    unsigned* AwB = dsm;
    unsigned* BwB = dsm + NSTAGE * AW_WORDS;
    const uint32_t a_base = smem_u32(AwB);
    const uint32_t b_base = smem_u32(BwB);

    const int mt = blockIdx.x;
    const int nt = blockIdx.y;

    const int tid  = threadIdx.x;
    const int lane = tid & 31;
    const int warp = tid >> 5;
    const int wm   = warp >> 2;
    const int wn   = warp & 3;
    const int lq   = lane >> 2;
    const int lr   = lane & 3;

    float acc[4][4][4];
#pragma unroll
    for (int mf = 0; mf < 4; mf++)
#pragma unroll
        for (int nf = 0; nf < 4; nf++)
#pragma unroll
            for (int j = 0; j < 4; j++) acc[mf][nf][j] = 0.f;

    proj_issue(a_base, b_base, mt, nt, 0, tid);
    CP_COMMIT();
    proj_issue(a_base + AW_WORDS * 4, b_base + BW_WORDS * 4, mt, nt, 32, tid);
    CP_COMMIT();

    for (int ci = 0; ci < 32; ci++) {
        if (ci < 30) CP_WAIT1(); else CP_WAIT0();
        __syncthreads();
        if (ci + 2 < 32) {
            int s = (ci + 2) % NSTAGE;
            proj_issue(a_base + s * AW_WORDS * 4, b_base + s * BW_WORDS * 4,
                       mt, nt, (ci + 2) * 32, tid);
            CP_COMMIT();
        }
        int s = ci % NSTAGE;
        gemm_mma_chunk(AwB + s * AW_WORDS, BwB + s * BW_WORDS, acc, wm, wn, lq, lr);
    }

#pragma unroll
    for (int mf = 0; mf < 4; mf++) {
#pragma unroll
        for (int nf = 0; nf < 4; nf++) {
            int row = wm * 64 + mf * 16 + lq;
            int col = nt * 128 + wn * 32 + nf * 8 + 2 * lr;
            float b0 = bo[col], b1 = bo[col + 1];
            float* C0 = out + (size_t)(mt * 128 + row) * DD + col;
            float* C1 = out + (size_t)(mt * 128 + row + 8) * DD + col;
            *reinterpret_cast<float2*>(C0) =
                make_float2(acc[mf][nf][0] + b0, acc[mf][nf][1] + b1);
            *reinterpret_cast<float2*>(C1) =
                make_float2(acc[mf][nf][2] + b0, acc[mf][nf][3] + b1);
        }
    }
}

// ---------------------------------------------------------------------------
// Causal flash attention, fp16 m16n8k16 (unchanged from R7).
// ---------------------------------------------------------------------------
__global__ void attn_kernel()
{
    __shared__ unsigned Qs[64 * 36];
    __shared__ unsigned Ks[64 * 36];
    __shared__ unsigned Vs[32 * 72];

    const int it = blockIdx.x;
    const int bh = blockIdx.y;
    const int b = bh >> 4, h = bh & 15;

    const __half* Q  = g_q + (size_t)bh * TT * HSS + (size_t)it * 64 * HSS;
    const __half* Kg = g_k + (size_t)bh * TT * HSS;
    const __half* Vg = g_v + (size_t)bh * TT * HSS;

    const int tid  = threadIdx.x;
    const int lane = tid & 31;
    const int warp = tid >> 5;
    const int lq   = lane >> 2;
    const int lr   = lane & 3;
    const int mrow = warp * 16 + lq;

#pragma unroll
    for (int i = 0; i < 4; i++) {
        int l = tid + i * 128;
        int row = l >> 3;
        int u   = l & 7;
        uint4 v = *reinterpret_cast<const uint4*>(&Q[(size_t)row * HSS + u * 8]);
        *reinterpret_cast<uint4*>(&Qs[row * 36 + u * 4]) = v;
    }

    float m0 = -1e30f, m1 = -1e30f, l0 = 0.f, l1 = 0.f;
    float o[8][4];
#pragma unroll
    for (int j = 0; j < 8; j++)
#pragma unroll
        for (int c = 0; c < 4; c++) o[j][c] = 0.f;

    const int ntiles = it + 1;
    for (int jt = 0; jt < ntiles; jt++) {
        __syncthreads();
        const __half* Kt = Kg + (size_t)jt * 64 * HSS;
        const __half* Vt = Vg + (size_t)jt * 64 * HSS;
#pragma unroll
        for (int i = 0; i < 4; i++) {
            int l = tid + i * 128;
            int row = l >> 3;
            int u   = l & 7;
            uint4 v = *reinterpret_cast<const uint4*>(&Kt[(size_t)row * HSS + u * 8]);
            *reinterpret_cast<uint4*>(&Ks[row * 36 + u * 4]) = v;
        }
#pragma unroll
        for (int i = 0; i < 2; i++) {
            int l = tid + i * 128;
            int kp = l >> 3;
            int no = l & 7;
            uint4 r0 = *reinterpret_cast<const uint4*>(&Vt[(size_t)(2 * kp) * HSS + no * 8]);
            uint4 r1 = *reinterpret_cast<const uint4*>(&Vt[(size_t)(2 * kp + 1) * HSS + no * 8]);
            uint4 w0, w1;
            w0.x = __byte_perm(r0.x, r1.x, 0x5410);
            w0.y = __byte_perm(r0.x, r1.x, 0x7632);
            w0.z = __byte_perm(r0.y, r1.y, 0x5410);
            w0.w = __byte_perm(r0.y, r1.y, 0x7632);
            w1.x = __byte_perm(r0.z, r1.z, 0x5410);
            w1.y = __byte_perm(r0.z, r1.z, 0x7632);
            w1.z = __byte_perm(r0.w, r1.w, 0x5410);
            w1.w = __byte_perm(r0.w, r1.w, 0x7632);
            *reinterpret_cast<uint4*>(&Vs[kp * 72 + no * 8])     = w0;
            *reinterpret_cast<uint4*>(&Vs[kp * 72 + no * 8 + 4]) = w1;
        }
        __syncthreads();

        float s[8][4];
#pragma unroll
        for (int j = 0; j < 8; j++)
#pragma unroll
            for (int c = 0; c < 4; c++) s[j][c] = 0.f;

#pragma unroll
        for (int c = 0; c < 4; c++) {
            const int kb = c * 8 + lr;
            unsigned a[4];
            a[0] = Qs[mrow * 36 + kb];
            a[1] = Qs[(mrow + 8) * 36 + kb];
            a[2] = Qs[mrow * 36 + kb + 4];
            a[3] = Qs[(mrow + 8) * 36 + kb + 4];
#pragma unroll
            for (int j = 0; j < 8; j++) {
                unsigned bb[2];
                bb[0] = Ks[(j * 8 + lq) * 36 + kb];
                bb[1] = Ks[(j * 8 + lq) * 36 + kb + 4];
                mma16h(s[j], a, bb);
            }
        }

        const float scale = 0.125f;
#pragma unroll
        for (int j = 0; j < 8; j++)
#pragma unroll
            for (int c = 0; c < 4; c++) s[j][c] *= scale;

        if (jt == it) {
            int r0g = mrow, r1g = mrow + 8;
#pragma unroll
            for (int j = 0; j < 8; j++) {
                int c0 = j * 8 + 2 * lr, c1 = c0 + 1;
                if (c0 > r0g) s[j][0] = -1e30f;
                if (c1 > r0g) s[j][1] = -1e30f;
                if (c0 > r1g) s[j][2] = -1e30f;
                if (c1 > r1g) s[j][3] = -1e30f;
            }
        }

        float mx0 = -1e30f, mx1 = -1e30f;
#pragma unroll
        for (int j = 0; j < 8; j++) {
            mx0 = fmaxf(mx0, fmaxf(s[j][0], s[j][1]));
            mx1 = fmaxf(mx1, fmaxf(s[j][2], s[j][3]));
        }
        mx0 = fmaxf(mx0, __shfl_xor_sync(0xffffffffu, mx0, 1));
        mx0 = fmaxf(mx0, __shfl_xor_sync(0xffffffffu, mx0, 2));
        mx1 = fmaxf(mx1, __shfl_xor_sync(0xffffffffu, mx1, 1));
        mx1 = fmaxf(mx1, __shfl_xor_sync(0xffffffffu, mx1, 2));

        float mn0 = fmaxf(m0, mx0), mn1 = fmaxf(m1, mx1);
        float f0 = __expf(m0 - mn0), f1 = __expf(m1 - mn1);

        float rs0 = 0.f, rs1 = 0.f;
#pragma unroll
        for (int j = 0; j < 8; j++) {
            s[j][0] = __expf(s[j][0] - mn0);
            s[j][1] = __expf(s[j][1] - mn0);
            s[j][2] = __expf(s[j][2] - mn1);
            s[j][3] = __expf(s[j][3] - mn1);
            rs0 += s[j][0] + s[j][1];
            rs1 += s[j][2] + s[j][3];
        }
        rs0 += __shfl_xor_sync(0xffffffffu, rs0, 1);
        rs0 += __shfl_xor_sync(0xffffffffu, rs0, 2);
        rs1 += __shfl_xor_sync(0xffffffffu, rs1, 1);
        rs1 += __shfl_xor_sync(0xffffffffu, rs1, 2);

        l0 = l0 * f0 + rs0;
        l1 = l1 * f1 + rs1;
        m0 = mn0; m1 = mn1;
#pragma unroll
        for (int j = 0; j < 8; j++) {
            o[j][0] *= f0; o[j][1] *= f0;
            o[j][2] *= f1; o[j][3] *= f1;
        }

#pragma unroll
        for (int c = 0; c < 4; c++) {
            unsigned a[4];
            a[0] = packh2(s[2 * c][0],     s[2 * c][1]);
            a[1] = packh2(s[2 * c][2],     s[2 * c][3]);
            a[2] = packh2(s[2 * c + 1][0], s[2 * c + 1][1]);
            a[3] = packh2(s[2 * c + 1][2], s[2 * c + 1][3]);
            const int kb = c * 8 + lr;
#pragma unroll
            for (int j = 0; j < 8; j++) {
                unsigned bb[2];
                bb[0] = Vs[kb * 72 + j * 8 + lq];
                bb[1] = Vs[(kb + 4) * 72 + j * 8 + lq];
                mma16h(o[j], a, bb);
            }
        }
    }

    float inv0 = 1.f / l0, inv1 = 1.f / l1;
    size_t row0 = (size_t)b * TT + (size_t)it * 64 + mrow;
    size_t row1 = row0 + 8;
#pragma unroll
    for (int j = 0; j < 8; j++) {
        int cb = h * HSS + j * 8 + 2 * lr;
        *reinterpret_cast<__half2*>(&g_att[row0 * DD + cb]) =
            __floats2half2_rn(o[j][0] * inv0, o[j][1] * inv0);
        *reinterpret_cast<__half2*>(&g_att[row1 * DD + cb]) =
            __floats2half2_rn(o[j][2] * inv1, o[j][3] * inv1);
    }
}

extern "C" void kernel_launch(void* const* d_in, const int* in_sizes, int n_in,
                              void* d_out, int out_size)
{
    const float* x  = (const float*)d_in[0];
    const float* Wq = (const float*)d_in[1];
    const float* Wk = (const float*)d_in[2];
    const float* Wv = (const float*)d_in[3];
    const float* Wo = (const float*)d_in[4];
    const float* bo = (const float*)d_in[5];
    float* out = (float*)d_out;

    cudaFuncSetAttribute(qkv_kernel,
                         cudaFuncAttributeMaxDynamicSharedMemorySize, PIPE_SMEM);
    cudaFuncSetAttribute(proj_kernel,
                         cudaFuncAttributeMaxDynamicSharedMemorySize, PIPE_SMEM);

    conv_kernel<<<512, 256>>>(x, Wq, Wk, Wv, Wo);

    dim3 g1((BB * TT) / 128, 24);
    qkv_kernel<<<g1, 256, PIPE_SMEM>>>();

    dim3 g2(TT / 64, BB * HH);
    attn_kernel<<<g2, 128>>>();

    dim3 g3((BB * TT) / 128, DD / 128);
    proj_kernel<<<g3, 256, PIPE_SMEM>>>(bo, out);
}

// round 9
// speedup vs baseline: 2.1338x; 1.0214x over previous
#include <cuda_runtime.h>
#include <cuda_fp16.h>
#include <math.h>
#include <cstdint>

#define BB 4
#define TT 1024
#define DD 1024
#define HH 16
#define HSS 64

// Scratch (no cudaMalloc allowed)
__device__ __align__(16) __half g_xh[BB*TT*DD];            // x in fp16
__device__ __align__(16) unsigned g_wp[3*HH*512*HSS];      // W q/k/v paired: [which][h][kp][hs]
__device__ __align__(16) unsigned g_wop[512*DD];           // Wo paired: [kp][n]
__device__ __align__(16) __half g_q[BB*HH*TT*HSS];
__device__ __align__(16) __half g_k[BB*HH*TT*HSS];
__device__ __align__(16) __half g_v[BB*HH*TT*HSS];
__device__ __align__(16) __half g_att[BB*TT*DD];

// ---------------------------------------------------------------------------
// helpers
// ---------------------------------------------------------------------------
__device__ __forceinline__ void mma16h(float* d, const unsigned* a, const unsigned* b) {
    asm volatile(
        "mma.sync.aligned.m16n8k16.row.col.f32.f16.f16.f32 "
        "{%0,%1,%2,%3}, {%4,%5,%6,%7}, {%8,%9}, {%0,%1,%2,%3};"
        : "+f"(d[0]), "+f"(d[1]), "+f"(d[2]), "+f"(d[3])
        : "r"(a[0]), "r"(a[1]), "r"(a[2]), "r"(a[3]),
          "r"(b[0]), "r"(b[1]));
}

__device__ __forceinline__ unsigned packh2(float a, float b) {
    __half2 h = __floats2half2_rn(a, b);
    return *reinterpret_cast<unsigned*>(&h);
}

__device__ __forceinline__ uint32_t smem_u32(const void* p) {
    uint32_t a;
    asm("{ .reg .u64 t; cvta.to.shared.u64 t, %1; cvt.u32.u64 %0, t; }"
        : "=r"(a) : "l"(p));
    return a;
}

__device__ __forceinline__ void cp16(uint32_t s, const void* g) {
    asm volatile("cp.async.cg.shared.global [%0], [%1], 16;"
                 :: "r"(s), "l"(g) : "memory");
}
#define CP_COMMIT() asm volatile("cp.async.commit_group;" ::: "memory")
#define CP_WAIT1()  asm volatile("cp.async.wait_group 1;" ::: "memory")
#define CP_WAIT0()  asm volatile("cp.async.wait_group 0;" ::: "memory")

// ---------------------------------------------------------------------------
// Convert/pack kernel (vectorized)
// ---------------------------------------------------------------------------
__global__ void conv_kernel(const float* __restrict__ x,
                            const float* __restrict__ Wq,
                            const float* __restrict__ Wk,
                            const float* __restrict__ Wv,
                            const float* __restrict__ Wo)
{
    const int stride = gridDim.x * blockDim.x;
    const int tid0 = blockIdx.x * blockDim.x + threadIdx.x;

    const int XN4 = (BB * TT * DD) / 4;
    for (int i = tid0; i < XN4; i += stride) {
        float4 v = reinterpret_cast<const float4*>(x)[i];
        uint2 o;
        o.x = packh2(v.x, v.y);
        o.y = packh2(v.z, v.w);
        reinterpret_cast<uint2*>(g_xh)[i] = o;
    }

    const int WP4 = (3 * HH * 512 * HSS) / 4;
    for (int i = tid0; i < WP4; i += stride) {
        int w0 = i * 4;
        int hs = w0 & 63;
        int kp = (w0 >> 6) & 511;
        int h  = (w0 >> 15) & 15;
        int which = w0 >> 19;
        const float* W = (which == 0 ? Wq : which == 1 ? Wk : Wv);
        const float* s0 = W + ((size_t)h * DD + 2 * kp) * HSS + hs;
        float4 a = *reinterpret_cast<const float4*>(s0);
        float4 b = *reinterpret_cast<const float4*>(s0 + HSS);
        uint4 o;
        o.x = packh2(a.x, b.x); o.y = packh2(a.y, b.y);
        o.z = packh2(a.z, b.z); o.w = packh2(a.w, b.w);
        reinterpret_cast<uint4*>(g_wp)[i] = o;
    }

    const int WO4 = (512 * DD) / 4;
    for (int i = tid0; i < WO4; i += stride) {
        int w0 = i * 4;
        int n  = w0 & 1023;
        int kp = w0 >> 10;
        const float* s0 = Wo + (size_t)(2 * kp) * DD + n;
        float4 a = *reinterpret_cast<const float4*>(s0);
        float4 b = *reinterpret_cast<const float4*>(s0 + DD);
        uint4 o;
        o.x = packh2(a.x, b.x); o.y = packh2(a.y, b.y);
        o.z = packh2(a.z, b.z); o.w = packh2(a.w, b.w);
        reinterpret_cast<uint4*>(g_wop)[i] = o;
    }
}

// ---------------------------------------------------------------------------
// fp16 GEMM: block 128x128, 8 warps = 2(m) x 4(n), warp 64x32, BK=64.
// Aw[row 128][kp 32 + pad4]  banks (4*row + kp) -> conflict-free frags
// Bw[kp 32][n 128 + pad8]    banks (8*kp + n)   -> conflict-free frags
// 3-stage cp.async pipeline, 16 k-chunks.
// ---------------------------------------------------------------------------
#define AW_STRIDE 36
#define BW_STRIDE 136
#define AW_WORDS  (128 * AW_STRIDE)     // 4608
#define BW_WORDS  (32 * BW_STRIDE)      // 4352
#define NSTAGE 3
#define NCHUNK 16
#define PIPE_SMEM ((AW_WORDS + BW_WORDS) * NSTAGE * 4)   // 107520 bytes

__device__ __forceinline__ void gemm_mma_chunk(
    const unsigned* __restrict__ Aw, const unsigned* __restrict__ Bw,
    float acc[4][4][4], int wm, int wn, int lq, int lr)
{
#pragma unroll
    for (int kc = 0; kc < 4; kc++) {
        const int kb = kc * 8 + lr;
        unsigned a[4][4];
#pragma unroll
        for (int mf = 0; mf < 4; mf++) {
            int mr = wm * 64 + mf * 16 + lq;
            a[mf][0] = Aw[mr * AW_STRIDE + kb];
            a[mf][1] = Aw[(mr + 8) * AW_STRIDE + kb];
            a[mf][2] = Aw[mr * AW_STRIDE + kb + 4];
            a[mf][3] = Aw[(mr + 8) * AW_STRIDE + kb + 4];
        }
        unsigned b[4][2];
#pragma unroll
        for (int nf = 0; nf < 4; nf++) {
            int nc = wn * 32 + nf * 8 + lq;
            b[nf][0] = Bw[kb * BW_STRIDE + nc];
            b[nf][1] = Bw[(kb + 4) * BW_STRIDE + nc];
        }
#pragma unroll
        for (int mf = 0; mf < 4; mf++)
#pragma unroll
            for (int nf = 0; nf < 4; nf++)
                mma16h(acc[mf][nf], a[mf], b[nf]);
    }
}

// ---------------------------------------------------------------------------
// QKV: logical GEMM [4096 x 3072 x 1024]. grid (32, 24).
// ---------------------------------------------------------------------------
__device__ __forceinline__ void qkv_issue(
    uint32_t a_s, uint32_t b_s, int mt, const unsigned* Wp, int h0, int k0, int tid)
{
#pragma unroll
    for (int i = 0; i < 4; i++) {
        int u = tid + i * 256;                 // 0..1023
        int row = u >> 3;                      // 0..127
        int q4  = u & 7;                       // 0..7
        cp16(a_s + (row * AW_STRIDE + q4 * 4) * 4,
             &g_xh[(size_t)(mt * 128 + row) * DD + k0 + q4 * 8]);
    }
#pragma unroll
    for (int i = 0; i < 4; i++) {
        int u = tid + i * 256;
        int kp = u >> 5;                       // 0..31
        int n  = (u & 31) * 4;
        int h  = h0 + (n >> 6);
        int hs = n & 63;
        cp16(b_s + (kp * BW_STRIDE + n) * 4,
             &Wp[((size_t)h * 512 + (k0 >> 1) + kp) * HSS + hs]);
    }
}

__global__ __launch_bounds__(256, 2) void qkv_kernel()
{
    extern __shared__ unsigned dsm[];
    unsigned* AwB = dsm;
    unsigned* BwB = dsm + NSTAGE * AW_WORDS;
    const uint32_t a_base = smem_u32(AwB);
    const uint32_t b_base = smem_u32(BwB);

    const int mt = blockIdx.x;
    const int nt = blockIdx.y;
    const int which = nt >> 3;
    const int h0 = (nt & 7) * 2;

    __half* dst = (which == 0 ? g_q : which == 1 ? g_k : g_v);
    const unsigned* Wp = g_wp + (size_t)which * HH * 512 * HSS;

    const int tid  = threadIdx.x;
    const int lane = tid & 31;
    const int warp = tid >> 5;
    const int wm   = warp >> 2;
    const int wn   = warp & 3;
    const int lq   = lane >> 2;
    const int lr   = lane & 3;

    float acc[4][4][4];
#pragma unroll
    for (int mf = 0; mf < 4; mf++)
#pragma unroll
        for (int nf = 0; nf < 4; nf++)
#pragma unroll
            for (int j = 0; j < 4; j++) acc[mf][nf][j] = 0.f;

    qkv_issue(a_base, b_base, mt, Wp, h0, 0, tid);
    CP_COMMIT();
    qkv_issue(a_base + AW_WORDS * 4, b_base + BW_WORDS * 4, mt, Wp, h0, 64, tid);
    CP_COMMIT();

    for (int ci = 0; ci < NCHUNK; ci++) {
        if (ci < NCHUNK - 2) CP_WAIT1(); else CP_WAIT0();
        __syncthreads();
        if (ci + 2 < NCHUNK) {
            int s = (ci + 2) % NSTAGE;
            qkv_issue(a_base + s * AW_WORDS * 4, b_base + s * BW_WORDS * 4,
                      mt, Wp, h0, (ci + 2) * 64, tid);
            CP_COMMIT();
        }
        int s = ci % NSTAGE;
        gemm_mma_chunk(AwB + s * AW_WORDS, BwB + s * BW_WORDS, acc, wm, wn, lq, lr);
    }

#pragma unroll
    for (int mf = 0; mf < 4; mf++) {
#pragma unroll
        for (int nf = 0; nf < 4; nf++) {
            int row = wm * 64 + mf * 16 + lq;
            int col = wn * 32 + nf * 8 + 2 * lr;
            int h   = h0 + (col >> 6);
            int hs  = col & 63;
#pragma unroll
            for (int half = 0; half < 2; half++) {
                int gr = mt * 128 + row + half * 8;
                int b = gr >> 10, t = gr & 1023;
                __half2* dp = reinterpret_cast<__half2*>(
                    dst + ((size_t)(b * HH + h) * TT + t) * HSS + hs);
                *dp = __floats2half2_rn(acc[mf][nf][half * 2],
                                        acc[mf][nf][half * 2 + 1]);
            }
        }
    }
}

// ---------------------------------------------------------------------------
// Output projection: out[4096,1024] = g_att @ Wo + bo.  grid (32, 8).
// ---------------------------------------------------------------------------
__device__ __forceinline__ void proj_issue(
    uint32_t a_s, uint32_t b_s, int mt, int nt, int k0, int tid)
{
#pragma unroll
    for (int i = 0; i < 4; i++) {
        int u = tid + i * 256;
        int row = u >> 3;
        int q4  = u & 7;
        cp16(a_s + (row * AW_STRIDE + q4 * 4) * 4,
             &g_att[(size_t)(mt * 128 + row) * DD + k0 + q4 * 8]);
    }
#pragma unroll
    for (int i = 0; i < 4; i++) {
        int u = tid + i * 256;
        int kp = u >> 5;
        int n  = (u & 31) * 4;
        cp16(b_s + (kp * BW_STRIDE + n) * 4,
             &g_wop[((size_t)(k0 >> 1) + kp) * DD + nt * 128 + n]);
    }
}

__global__ __launch_bounds__(256, 2) void proj_kernel(
    const float* __restrict__ bo, float* __restrict__ out)
{
    extern __shared__ unsigned dsm[];
    unsigned* AwB = dsm;
    unsigned* BwB = dsm + NSTAGE * AW_WORDS;
    const uint32_t a_base = smem_u32(AwB);
    const uint32_t b_base = smem_u32(BwB);

    const int mt = blockIdx.x;
    const int nt = blockIdx.y;

    const int tid  = threadIdx.x;
    const int lane = tid & 31;
    const int warp = tid >> 5;
    const int wm   = warp >> 2;
    const int wn   = warp & 3;
    const int lq   = lane >> 2;
    const int lr   = lane & 3;

    float acc[4][4][4];
#pragma unroll
    for (int mf = 0; mf < 4; mf++)
#pragma unroll
        for (int nf = 0; nf < 4; nf++)
#pragma unroll
            for (int j = 0; j < 4; j++) acc[mf][nf][j] = 0.f;

    proj_issue(a_base, b_base, mt, nt, 0, tid);
    CP_COMMIT();
    proj_issue(a_base + AW_WORDS * 4, b_base + BW_WORDS * 4, mt, nt, 64, tid);
    CP_COMMIT();

    for (int ci = 0; ci < NCHUNK; ci++) {
        if (ci < NCHUNK - 2) CP_WAIT1(); else CP_WAIT0();
        __syncthreads();
        if (ci + 2 < NCHUNK) {
            int s = (ci + 2) % NSTAGE;
            proj_issue(a_base + s * AW_WORDS * 4, b_base + s * BW_WORDS * 4,
                       mt, nt, (ci + 2) * 64, tid);
            CP_COMMIT();
        }
        int s = ci % NSTAGE;
        gemm_mma_chunk(AwB + s * AW_WORDS, BwB + s * BW_WORDS, acc, wm, wn, lq, lr);
    }

#pragma unroll
    for (int mf = 0; mf < 4; mf++) {
#pragma unroll
        for (int nf = 0; nf < 4; nf++) {
            int row = wm * 64 + mf * 16 + lq;
            int col = nt * 128 + wn * 32 + nf * 8 + 2 * lr;
            float b0 = bo[col], b1 = bo[col + 1];
            float* C0 = out + (size_t)(mt * 128 + row) * DD + col;
            float* C1 = out + (size_t)(mt * 128 + row + 8) * DD + col;
            *reinterpret_cast<float2*>(C0) =
                make_float2(acc[mf][nf][0] + b0, acc[mf][nf][1] + b1);
            *reinterpret_cast<float2*>(C1) =
                make_float2(acc[mf][nf][2] + b0, acc[mf][nf][3] + b1);
        }
    }
}

// ---------------------------------------------------------------------------
// Causal flash attention, fp16 m16n8k16 (unchanged from R7/R8).
// ---------------------------------------------------------------------------
__global__ void attn_kernel()
{
    __shared__ unsigned Qs[64 * 36];
    __shared__ unsigned Ks[64 * 36];
    __shared__ unsigned Vs[32 * 72];

    const int it = blockIdx.x;
    const int bh = blockIdx.y;
    const int b = bh >> 4, h = bh & 15;

    const __half* Q  = g_q + (size_t)bh * TT * HSS + (size_t)it * 64 * HSS;
    const __half* Kg = g_k + (size_t)bh * TT * HSS;
    const __half* Vg = g_v + (size_t)bh * TT * HSS;

    const int tid  = threadIdx.x;
    const int lane = tid & 31;
    const int warp = tid >> 5;
    const int lq   = lane >> 2;
    const int lr   = lane & 3;
    const int mrow = warp * 16 + lq;

#pragma unroll
    for (int i = 0; i < 4; i++) {
        int l = tid + i * 128;
        int row = l >> 3;
        int u   = l & 7;
        uint4 v = *reinterpret_cast<const uint4*>(&Q[(size_t)row * HSS + u * 8]);
        *reinterpret_cast<uint4*>(&Qs[row * 36 + u * 4]) = v;
    }

    float m0 = -1e30f, m1 = -1e30f, l0 = 0.f, l1 = 0.f;
    float o[8][4];
#pragma unroll
    for (int j = 0; j < 8; j++)
#pragma unroll
        for (int c = 0; c < 4; c++) o[j][c] = 0.f;

    const int ntiles = it + 1;
    for (int jt = 0; jt < ntiles; jt++) {
        __syncthreads();
        const __half* Kt = Kg + (size_t)jt * 64 * HSS;
        const __half* Vt = Vg + (size_t)jt * 64 * HSS;
#pragma unroll
        for (int i = 0; i < 4; i++) {
            int l = tid + i * 128;
            int row = l >> 3;
            int u   = l & 7;
            uint4 v = *reinterpret_cast<const uint4*>(&Kt[(size_t)row * HSS + u * 8]);
            *reinterpret_cast<uint4*>(&Ks[row * 36 + u * 4]) = v;
        }
#pragma unroll
        for (int i = 0; i < 2; i++) {
            int l = tid + i * 128;
            int kp = l >> 3;
            int no = l & 7;
            uint4 r0 = *reinterpret_cast<const uint4*>(&Vt[(size_t)(2 * kp) * HSS + no * 8]);
            uint4 r1 = *reinterpret_cast<const uint4*>(&Vt[(size_t)(2 * kp + 1) * HSS + no * 8]);
            uint4 w0, w1;
            w0.x = __byte_perm(r0.x, r1.x, 0x5410);
            w0.y = __byte_perm(r0.x, r1.x, 0x7632);
            w0.z = __byte_perm(r0.y, r1.y, 0x5410);
            w0.w = __byte_perm(r0.y, r1.y, 0x7632);
            w1.x = __byte_perm(r0.z, r1.z, 0x5410);
            w1.y = __byte_perm(r0.z, r1.z, 0x7632);
            w1.z = __byte_perm(r0.w, r1.w, 0x5410);
            w1.w = __byte_perm(r0.w, r1.w, 0x7632);
            *reinterpret_cast<uint4*>(&Vs[kp * 72 + no * 8])     = w0;
            *reinterpret_cast<uint4*>(&Vs[kp * 72 + no * 8 + 4]) = w1;
        }
        __syncthreads();

        float s[8][4];
#pragma unroll
        for (int j = 0; j < 8; j++)
#pragma unroll
            for (int c = 0; c < 4; c++) s[j][c] = 0.f;

#pragma unroll
        for (int c = 0; c < 4; c++) {
            const int kb = c * 8 + lr;
            unsigned a[4];
            a[0] = Qs[mrow * 36 + kb];
            a[1] = Qs[(mrow + 8) * 36 + kb];
            a[2] = Qs[mrow * 36 + kb + 4];
            a[3] = Qs[(mrow + 8) * 36 + kb + 4];
#pragma unroll
            for (int j = 0; j < 8; j++) {
                unsigned bb[2];
                bb[0] = Ks[(j * 8 + lq) * 36 + kb];
                bb[1] = Ks[(j * 8 + lq) * 36 + kb + 4];
                mma16h(s[j], a, bb);
            }
        }

        const float scale = 0.125f;
#pragma unroll
        for (int j = 0; j < 8; j++)
#pragma unroll
            for (int c = 0; c < 4; c++) s[j][c] *= scale;

        if (jt == it) {
            int r0g = mrow, r1g = mrow + 8;
#pragma unroll
            for (int j = 0; j < 8; j++) {
                int c0 = j * 8 + 2 * lr, c1 = c0 + 1;
                if (c0 > r0g) s[j][0] = -1e30f;
                if (c1 > r0g) s[j][1] = -1e30f;
                if (c0 > r1g) s[j][2] = -1e30f;
                if (c1 > r1g) s[j][3] = -1e30f;
            }
        }

        float mx0 = -1e30f, mx1 = -1e30f;
#pragma unroll
        for (int j = 0; j < 8; j++) {
            mx0 = fmaxf(mx0, fmaxf(s[j][0], s[j][1]));
            mx1 = fmaxf(mx1, fmaxf(s[j][2], s[j][3]));
        }
        mx0 = fmaxf(mx0, __shfl_xor_sync(0xffffffffu, mx0, 1));
        mx0 = fmaxf(mx0, __shfl_xor_sync(0xffffffffu, mx0, 2));
        mx1 = fmaxf(mx1, __shfl_xor_sync(0xffffffffu, mx1, 1));
        mx1 = fmaxf(mx1, __shfl_xor_sync(0xffffffffu, mx1, 2));

        float mn0 = fmaxf(m0, mx0), mn1 = fmaxf(m1, mx1);
        float f0 = __expf(m0 - mn0), f1 = __expf(m1 - mn1);

        float rs0 = 0.f, rs1 = 0.f;
#pragma unroll
        for (int j = 0; j < 8; j++) {
            s[j][0] = __expf(s[j][0] - mn0);
            s[j][1] = __expf(s[j][1] - mn0);
            s[j][2] = __expf(s[j][2] - mn1);
            s[j][3] = __expf(s[j][3] - mn1);
            rs0 += s[j][0] + s[j][1];
            rs1 += s[j][2] + s[j][3];
        }
        rs0 += __shfl_xor_sync(0xffffffffu, rs0, 1);
        rs0 += __shfl_xor_sync(0xffffffffu, rs0, 2);
        rs1 += __shfl_xor_sync(0xffffffffu, rs1, 1);
        rs1 += __shfl_xor_sync(0xffffffffu, rs1, 2);

        l0 = l0 * f0 + rs0;
        l1 = l1 * f1 + rs1;
        m0 = mn0; m1 = mn1;
#pragma unroll
        for (int j = 0; j < 8; j++) {
            o[j][0] *= f0; o[j][1] *= f0;
            o[j][2] *= f1; o[j][3] *= f1;
        }

#pragma unroll
        for (int c = 0; c < 4; c++) {
            unsigned a[4];
            a[0] = packh2(s[2 * c][0],     s[2 * c][1]);
            a[1] = packh2(s[2 * c][2],     s[2 * c][3]);
            a[2] = packh2(s[2 * c + 1][0], s[2 * c + 1][1]);
            a[3] = packh2(s[2 * c + 1][2], s[2 * c + 1][3]);
            const int kb = c * 8 + lr;
#pragma unroll
            for (int j = 0; j < 8; j++) {
                unsigned bb[2];
                bb[0] = Vs[kb * 72 + j * 8 + lq];
                bb[1] = Vs[(kb + 4) * 72 + j * 8 + lq];
                mma16h(o[j], a, bb);
            }
        }
    }

    float inv0 = 1.f / l0, inv1 = 1.f / l1;
    size_t row0 = (size_t)b * TT + (size_t)it * 64 + mrow;
    size_t row1 = row0 + 8;
#pragma unroll
    for (int j = 0; j < 8; j++) {
        int cb = h * HSS + j * 8 + 2 * lr;
        *reinterpret_cast<__half2*>(&g_att[row0 * DD + cb]) =
            __floats2half2_rn(o[j][0] * inv0, o[j][1] * inv0);
        *reinterpret_cast<__half2*>(&g_att[row1 * DD + cb]) =
            __floats2half2_rn(o[j][2] * inv1, o[j][3] * inv1);
    }
}

extern "C" void kernel_launch(void* const* d_in, const int* in_sizes, int n_in,
                              void* d_out, int out_size)
{
    const float* x  = (const float*)d_in[0];
    const float* Wq = (const float*)d_in[1];
    const float* Wk = (const float*)d_in[2];
    const float* Wv = (const float*)d_in[3];
    const float* Wo = (const float*)d_in[4];
    const float* bo = (const float*)d_in[5];
    float* out = (float*)d_out;

    cudaFuncSetAttribute(qkv_kernel,
                         cudaFuncAttributeMaxDynamicSharedMemorySize, PIPE_SMEM);
    cudaFuncSetAttribute(proj_kernel,
                         cudaFuncAttributeMaxDynamicSharedMemorySize, PIPE_SMEM);

    conv_kernel<<<512, 256>>>(x, Wq, Wk, Wv, Wo);

    dim3 g1((BB * TT) / 128, 24);
    qkv_kernel<<<g1, 256, PIPE_SMEM>>>();

    dim3 g2(TT / 64, BB * HH);
    attn_kernel<<<g2, 128>>>();

    dim3 g3((BB * TT) / 128, DD / 128);
    proj_kernel<<<g3, 256, PIPE_SMEM>>>(bo, out);
}

// round 10
// speedup vs baseline: 2.1595x; 1.0121x over previous
#include <cuda_runtime.h>
#include <cuda_fp16.h>
#include <math.h>
#include <cstdint>

#define BB 4
#define TT 1024
#define DD 1024
#define HH 16
#define HSS 64

// Scratch (no cudaMalloc allowed)
__device__ __align__(16) __half g_xh[BB*TT*DD];            // x in fp16
__device__ __align__(16) unsigned g_wp[3*HH*512*HSS];      // W q/k/v paired: [which][h][kp][hs]
__device__ __align__(16) unsigned g_wop[512*DD];           // Wo paired: [kp][n]
__device__ __align__(16) __half g_q[BB*HH*TT*HSS];
__device__ __align__(16) __half g_k[BB*HH*TT*HSS];
__device__ __align__(16) __half g_v[BB*HH*TT*HSS];
__device__ __align__(16) __half g_att[BB*TT*DD];

// ---------------------------------------------------------------------------
// helpers
// ---------------------------------------------------------------------------
__device__ __forceinline__ void mma16h(float* d, const unsigned* a, const unsigned* b) {
    asm volatile(
        "mma.sync.aligned.m16n8k16.row.col.f32.f16.f16.f32 "
        "{%0,%1,%2,%3}, {%4,%5,%6,%7}, {%8,%9}, {%0,%1,%2,%3};"
        : "+f"(d[0]), "+f"(d[1]), "+f"(d[2]), "+f"(d[3])
        : "r"(a[0]), "r"(a[1]), "r"(a[2]), "r"(a[3]),
          "r"(b[0]), "r"(b[1]));
}

__device__ __forceinline__ void ldsm4(unsigned& r0, unsigned& r1,
                                      unsigned& r2, unsigned& r3, uint32_t addr) {
    asm volatile("ldmatrix.sync.aligned.m8n8.x4.shared.b16 {%0,%1,%2,%3}, [%4];"
                 : "=r"(r0), "=r"(r1), "=r"(r2), "=r"(r3) : "r"(addr));
}

__device__ __forceinline__ unsigned packh2(float a, float b) {
    __half2 h = __floats2half2_rn(a, b);
    return *reinterpret_cast<unsigned*>(&h);
}

__device__ __forceinline__ uint32_t smem_u32(const void* p) {
    uint32_t a;
    asm("{ .reg .u64 t; cvta.to.shared.u64 t, %1; cvt.u32.u64 %0, t; }"
        : "=r"(a) : "l"(p));
    return a;
}

__device__ __forceinline__ void cp16(uint32_t s, const void* g) {
    asm volatile("cp.async.cg.shared.global [%0], [%1], 16;"
                 :: "r"(s), "l"(g) : "memory");
}
#define CP_COMMIT() asm volatile("cp.async.commit_group;" ::: "memory")
#define CP_WAIT1()  asm volatile("cp.async.wait_group 1;" ::: "memory")
#define CP_WAIT0()  asm volatile("cp.async.wait_group 0;" ::: "memory")

// ---------------------------------------------------------------------------
// Convert/pack kernel (vectorized)
// ---------------------------------------------------------------------------
__global__ void conv_kernel(const float* __restrict__ x,
                            const float* __restrict__ Wq,
                            const float* __restrict__ Wk,
                            const float* __restrict__ Wv,
                            const float* __restrict__ Wo)
{
    const int stride = gridDim.x * blockDim.x;
    const int tid0 = blockIdx.x * blockDim.x + threadIdx.x;

    const int XN4 = (BB * TT * DD) / 4;
    for (int i = tid0; i < XN4; i += stride) {
        float4 v = reinterpret_cast<const float4*>(x)[i];
        uint2 o;
        o.x = packh2(v.x, v.y);
        o.y = packh2(v.z, v.w);
        reinterpret_cast<uint2*>(g_xh)[i] = o;
    }

    const int WP4 = (3 * HH * 512 * HSS) / 4;
    for (int i = tid0; i < WP4; i += stride) {
        int w0 = i * 4;
        int hs = w0 & 63;
        int kp = (w0 >> 6) & 511;
        int h  = (w0 >> 15) & 15;
        int which = w0 >> 19;
        const float* W = (which == 0 ? Wq : which == 1 ? Wk : Wv);
        const float* s0 = W + ((size_t)h * DD + 2 * kp) * HSS + hs;
        float4 a = *reinterpret_cast<const float4*>(s0);
        float4 b = *reinterpret_cast<const float4*>(s0 + HSS);
        uint4 o;
        o.x = packh2(a.x, b.x); o.y = packh2(a.y, b.y);
        o.z = packh2(a.z, b.z); o.w = packh2(a.w, b.w);
        reinterpret_cast<uint4*>(g_wp)[i] = o;
    }

    const int WO4 = (512 * DD) / 4;
    for (int i = tid0; i < WO4; i += stride) {
        int w0 = i * 4;
        int n  = w0 & 1023;
        int kp = w0 >> 10;
        const float* s0 = Wo + (size_t)(2 * kp) * DD + n;
        float4 a = *reinterpret_cast<const float4*>(s0);
        float4 b = *reinterpret_cast<const float4*>(s0 + DD);
        uint4 o;
        o.x = packh2(a.x, b.x); o.y = packh2(a.y, b.y);
        o.z = packh2(a.z, b.z); o.w = packh2(a.w, b.w);
        reinterpret_cast<uint4*>(g_wop)[i] = o;
    }
}

// ---------------------------------------------------------------------------
// fp16 GEMM: block 128x128, 8 warps = 2(m) x 4(n), warp 64x32, BK=64.
// Aw[row 128][kp 32 + pad4]  -> ldmatrix.x4 for A fragments
// Bw[kp 32][n 128 + pad8]    -> scalar frags (packed k-pairs)
// 3-stage cp.async pipeline, 16 k-chunks.
// ---------------------------------------------------------------------------
#define AW_STRIDE 36
#define BW_STRIDE 136
#define AW_WORDS  (128 * AW_STRIDE)     // 4608
#define BW_WORDS  (32 * BW_STRIDE)      // 4352
#define NSTAGE 3
#define NCHUNK 16
#define PIPE_SMEM ((AW_WORDS + BW_WORDS) * NSTAGE * 4)   // 107520 bytes

// A-ldmatrix per-lane offsets: rows m0/m1 = base..+15 (lane bit3), cols word
// +0/+4 (lane bit4). Delivers {a0,a1,a2,a3} of the m16k16 fragment.
__device__ __forceinline__ uint32_t a_lane_off(int lane) {
    int r = (lane & 7) + ((lane >> 3) & 1) * 8;   // row offset 0..15
    int c = (lane & 16) ? 4 : 0;                  // word-col offset
    return (uint32_t)(r * AW_STRIDE + c) * 4;
}

__device__ __forceinline__ void gemm_mma_chunk(
    uint32_t aw_addr0,                      // smem addr of Aw row (wm*64) col 0, + lane offset
    const unsigned* __restrict__ Bw,
    float acc[4][4][4], int wn, int lq, int lr)
{
#pragma unroll
    for (int kc = 0; kc < 4; kc++) {
        const int kb = kc * 8 + lr;
        unsigned a[4][4];
#pragma unroll
        for (int mf = 0; mf < 4; mf++)
            ldsm4(a[mf][0], a[mf][1], a[mf][2], a[mf][3],
                  aw_addr0 + (uint32_t)(mf * 16 * AW_STRIDE + kc * 8) * 4);
        unsigned b[4][2];
#pragma unroll
        for (int nf = 0; nf < 4; nf++) {
            int nc = wn * 32 + nf * 8 + lq;
            b[nf][0] = Bw[kb * BW_STRIDE + nc];
            b[nf][1] = Bw[(kb + 4) * BW_STRIDE + nc];
        }
#pragma unroll
        for (int mf = 0; mf < 4; mf++)
#pragma unroll
            for (int nf = 0; nf < 4; nf++)
                mma16h(acc[mf][nf], a[mf], b[nf]);
    }
}

// ---------------------------------------------------------------------------
// QKV: logical GEMM [4096 x 3072 x 1024]. grid (32, 24).
// ---------------------------------------------------------------------------
__device__ __forceinline__ void qkv_issue(
    uint32_t a_s, uint32_t b_s, int mt, const unsigned* Wp, int h0, int k0, int tid)
{
#pragma unroll
    for (int i = 0; i < 4; i++) {
        int u = tid + i * 256;
        int row = u >> 3;
        int q4  = u & 7;
        cp16(a_s + (row * AW_STRIDE + q4 * 4) * 4,
             &g_xh[(size_t)(mt * 128 + row) * DD + k0 + q4 * 8]);
    }
#pragma unroll
    for (int i = 0; i < 4; i++) {
        int u = tid + i * 256;
        int kp = u >> 5;
        int n  = (u & 31) * 4;
        int h  = h0 + (n >> 6);
        int hs = n & 63;
        cp16(b_s + (kp * BW_STRIDE + n) * 4,
             &Wp[((size_t)h * 512 + (k0 >> 1) + kp) * HSS + hs]);
    }
}

__global__ __launch_bounds__(256, 2) void qkv_kernel()
{
    extern __shared__ unsigned dsm[];
    unsigned* AwB = dsm;
    unsigned* BwB = dsm + NSTAGE * AW_WORDS;
    const uint32_t a_base = smem_u32(AwB);
    const uint32_t b_base = smem_u32(BwB);

    const int mt = blockIdx.x;
    const int nt = blockIdx.y;
    const int which = nt >> 3;
    const int h0 = (nt & 7) * 2;

    __half* dst = (which == 0 ? g_q : which == 1 ? g_k : g_v);
    const unsigned* Wp = g_wp + (size_t)which * HH * 512 * HSS;

    const int tid  = threadIdx.x;
    const int lane = tid & 31;
    const int warp = tid >> 5;
    const int wm   = warp >> 2;
    const int wn   = warp & 3;
    const int lq   = lane >> 2;
    const int lr   = lane & 3;
    const uint32_t aoff = (uint32_t)(wm * 64 * AW_STRIDE) * 4 + a_lane_off(lane);

    float acc[4][4][4];
#pragma unroll
    for (int mf = 0; mf < 4; mf++)
#pragma unroll
        for (int nf = 0; nf < 4; nf++)
#pragma unroll
            for (int j = 0; j < 4; j++) acc[mf][nf][j] = 0.f;

    qkv_issue(a_base, b_base, mt, Wp, h0, 0, tid);
    CP_COMMIT();
    qkv_issue(a_base + AW_WORDS * 4, b_base + BW_WORDS * 4, mt, Wp, h0, 64, tid);
    CP_COMMIT();

    for (int ci = 0; ci < NCHUNK; ci++) {
        if (ci < NCHUNK - 2) CP_WAIT1(); else CP_WAIT0();
        __syncthreads();
        if (ci + 2 < NCHUNK) {
            int s = (ci + 2) % NSTAGE;
            qkv_issue(a_base + s * AW_WORDS * 4, b_base + s * BW_WORDS * 4,
                      mt, Wp, h0, (ci + 2) * 64, tid);
            CP_COMMIT();
        }
        int s = ci % NSTAGE;
        gemm_mma_chunk(a_base + s * AW_WORDS * 4 + aoff,
                       BwB + s * BW_WORDS, acc, wn, lq, lr);
    }

#pragma unroll
    for (int mf = 0; mf < 4; mf++) {
#pragma unroll
        for (int nf = 0; nf < 4; nf++) {
            int row = wm * 64 + mf * 16 + lq;
            int col = wn * 32 + nf * 8 + 2 * lr;
            int h   = h0 + (col >> 6);
            int hs  = col & 63;
#pragma unroll
            for (int half = 0; half < 2; half++) {
                int gr = mt * 128 + row + half * 8;
                int b = gr >> 10, t = gr & 1023;
                __half2* dp = reinterpret_cast<__half2*>(
                    dst + ((size_t)(b * HH + h) * TT + t) * HSS + hs);
                *dp = __floats2half2_rn(acc[mf][nf][half * 2],
                                        acc[mf][nf][half * 2 + 1]);
            }
        }
    }
}

// ---------------------------------------------------------------------------
// Output projection: out[4096,1024] = g_att @ Wo + bo.  grid (32, 8).
// ---------------------------------------------------------------------------
__device__ __forceinline__ void proj_issue(
    uint32_t a_s, uint32_t b_s, int mt, int nt, int k0, int tid)
{
#pragma unroll
    for (int i = 0; i < 4; i++) {
        int u = tid + i * 256;
        int row = u >> 3;
        int q4  = u & 7;
        cp16(a_s + (row * AW_STRIDE + q4 * 4) * 4,
             &g_att[(size_t)(mt * 128 + row) * DD + k0 + q4 * 8]);
    }
#pragma unroll
    for (int i = 0; i < 4; i++) {
        int u = tid + i * 256;
        int kp = u >> 5;
        int n  = (u & 31) * 4;
        cp16(b_s + (kp * BW_STRIDE + n) * 4,
             &g_wop[((size_t)(k0 >> 1) + kp) * DD + nt * 128 + n]);
    }
}

__global__ __launch_bounds__(256, 2) void proj_kernel(
    const float* __restrict__ bo, float* __restrict__ out)
{
    extern __shared__ unsigned dsm[];
    unsigned* AwB = dsm;
    unsigned* BwB = dsm + NSTAGE * AW_WORDS;
    const uint32_t a_base = smem_u32(AwB);
    const uint32_t b_base = smem_u32(BwB);

    const int mt = blockIdx.x;
    const int nt = blockIdx.y;

    const int tid  = threadIdx.x;
    const int lane = tid & 31;
    const int warp = tid >> 5;
    const int wm   = warp >> 2;
    const int wn   = warp & 3;
    const int lq   = lane >> 2;
    const int lr   = lane & 3;
    const uint32_t aoff = (uint32_t)(wm * 64 * AW_STRIDE) * 4 + a_lane_off(lane);

    float acc[4][4][4];
#pragma unroll
    for (int mf = 0; mf < 4; mf++)
#pragma unroll
        for (int nf = 0; nf < 4; nf++)
#pragma unroll
            for (int j = 0; j < 4; j++) acc[mf][nf][j] = 0.f;

    proj_issue(a_base, b_base, mt, nt, 0, tid);
    CP_COMMIT();
    proj_issue(a_base + AW_WORDS * 4, b_base + BW_WORDS * 4, mt, nt, 64, tid);
    CP_COMMIT();

    for (int ci = 0; ci < NCHUNK; ci++) {
        if (ci < NCHUNK - 2) CP_WAIT1(); else CP_WAIT0();
        __syncthreads();
        if (ci + 2 < NCHUNK) {
            int s = (ci + 2) % NSTAGE;
            proj_issue(a_base + s * AW_WORDS * 4, b_base + s * BW_WORDS * 4,
                       mt, nt, (ci + 2) * 64, tid);
            CP_COMMIT();
        }
        int s = ci % NSTAGE;
        gemm_mma_chunk(a_base + s * AW_WORDS * 4 + aoff,
                       BwB + s * BW_WORDS, acc, wn, lq, lr);
    }

#pragma unroll
    for (int mf = 0; mf < 4; mf++) {
#pragma unroll
        for (int nf = 0; nf < 4; nf++) {
            int row = wm * 64 + mf * 16 + lq;
            int col = nt * 128 + wn * 32 + nf * 8 + 2 * lr;
            float b0 = bo[col], b1 = bo[col + 1];
            float* C0 = out + (size_t)(mt * 128 + row) * DD + col;
            float* C1 = out + (size_t)(mt * 128 + row + 8) * DD + col;
            *reinterpret_cast<float2*>(C0) =
                make_float2(acc[mf][nf][0] + b0, acc[mf][nf][1] + b1);
            *reinterpret_cast<float2*>(C1) =
                make_float2(acc[mf][nf][2] + b0, acc[mf][nf][3] + b1);
        }
    }
}

// ---------------------------------------------------------------------------
// Causal flash attention, fp16 m16n8k16. Block = 256 threads (8 warps),
// q-tile 128; warp w owns rows [16w, 16w+16). kv tiles of 64.
// Q & K fragments via ldmatrix; V scalar (packed k-pairs). P from regs.
// ---------------------------------------------------------------------------
__global__ __launch_bounds__(256) void attn_kernel()
{
    __shared__ unsigned Qs[128 * 36];
    __shared__ unsigned Ks[64 * 36];
    __shared__ unsigned Vs[32 * 72];

    const int it = gridDim.x - 1 - blockIdx.x;   // heavy tiles first
    const int bh = blockIdx.y;
    const int b = bh >> 4, h = bh & 15;

    const __half* Q  = g_q + (size_t)bh * TT * HSS + (size_t)it * 128 * HSS;
    const __half* Kg = g_k + (size_t)bh * TT * HSS;
    const __half* Vg = g_v + (size_t)bh * TT * HSS;

    const int tid  = threadIdx.x;
    const int lane = tid & 31;
    const int warp = tid >> 5;
    const int lq   = lane >> 2;
    const int lr   = lane & 3;
    const int mrow = warp * 16 + lq;             // local q rows mrow, mrow+8

    const uint32_t qs_base = smem_u32(Qs);
    const uint32_t ks_base = smem_u32(Ks);
    // Q ldmatrix lane addr (A-style): rows warp*16 + (0..15), col word +0/+4
    const uint32_t q_addr0 = qs_base + (uint32_t)(warp * 16 * 36) * 4 + a_lane_off(lane);
    // K ldmatrix lane addr: matrices (j,0),(j,4),(j+1,0),(j+1,4)
    {
    }
    const int krow_l = (lane & 7) + ((lane >> 4) & 1) * 8;    // row within j-pair
    const int kcol_l = ((lane >> 3) & 1) * 4;
    const uint32_t k_addr0 = ks_base + (uint32_t)(krow_l * 36 + kcol_l) * 4;

    // Load Q tile: 128 rows x 8 uint4
#pragma unroll
    for (int i = 0; i < 4; i++) {
        int l = tid + i * 256;
        int row = l >> 3;
        int u   = l & 7;
        uint4 v = *reinterpret_cast<const uint4*>(&Q[(size_t)row * HSS + u * 8]);
        *reinterpret_cast<uint4*>(&Qs[row * 36 + u * 4]) = v;
    }

    float m0 = -1e30f, m1 = -1e30f, l0 = 0.f, l1 = 0.f;
    float o[8][4];
#pragma unroll
    for (int j = 0; j < 8; j++)
#pragma unroll
        for (int c = 0; c < 4; c++) o[j][c] = 0.f;

    const int ntiles = 2 * it + 2;
    for (int jt = 0; jt < ntiles; jt++) {
        __syncthreads();
        const __half* Kt = Kg + (size_t)jt * 64 * HSS;
        const __half* Vt = Vg + (size_t)jt * 64 * HSS;
        // K: 64 rows x 8 uint4 = 512 units
#pragma unroll
        for (int i = 0; i < 2; i++) {
            int l = tid + i * 256;
            int row = l >> 3;
            int u   = l & 7;
            uint4 v = *reinterpret_cast<const uint4*>(&Kt[(size_t)row * HSS + u * 8]);
            *reinterpret_cast<uint4*>(&Ks[row * 36 + u * 4]) = v;
        }
        // V: 256 perm units (kp, n-oct)
        {
            int kp = tid >> 3;
            int no = tid & 7;
            uint4 r0 = *reinterpret_cast<const uint4*>(&Vt[(size_t)(2 * kp) * HSS + no * 8]);
            uint4 r1 = *reinterpret_cast<const uint4*>(&Vt[(size_t)(2 * kp + 1) * HSS + no * 8]);
            uint4 w0, w1;
            w0.x = __byte_perm(r0.x, r1.x, 0x5410);
            w0.y = __byte_perm(r0.x, r1.x, 0x7632);
            w0.z = __byte_perm(r0.y, r1.y, 0x5410);
            w0.w = __byte_perm(r0.y, r1.y, 0x7632);
            w1.x = __byte_perm(r0.z, r1.z, 0x5410);
            w1.y = __byte_perm(r0.z, r1.z, 0x7632);
            w1.z = __byte_perm(r0.w, r1.w, 0x5410);
            w1.w = __byte_perm(r0.w, r1.w, 0x7632);
            *reinterpret_cast<uint4*>(&Vs[kp * 72 + no * 8])     = w0;
            *reinterpret_cast<uint4*>(&Vs[kp * 72 + no * 8 + 4]) = w1;
        }
        __syncthreads();

        // Lower-half warps fully masked on the final (odd-diagonal) tile.
        if (jt == 2 * it + 1 && warp < 4) continue;

        // ---- S = Q K^T (ldmatrix A + ldmatrix K-pairs, 32 mmas)
        float s[8][4];
#pragma unroll
        for (int j = 0; j < 8; j++)
#pragma unroll
            for (int c = 0; c < 4; c++) s[j][c] = 0.f;

#pragma unroll
        for (int c = 0; c < 4; c++) {
            unsigned a[4];
            ldsm4(a[0], a[1], a[2], a[3], q_addr0 + (uint32_t)(c * 8) * 4);
#pragma unroll
            for (int jp = 0; jp < 4; jp++) {
                unsigned b0, b1, b2, b3;
                ldsm4(b0, b1, b2, b3,
                      k_addr0 + (uint32_t)(jp * 16 * 36 + c * 8) * 4);
                unsigned bb0[2] = {b0, b1};
                unsigned bb1[2] = {b2, b3};
                mma16h(s[2 * jp],     a, bb0);
                mma16h(s[2 * jp + 1], a, bb1);
            }
        }

        const float scale = 0.125f;
#pragma unroll
        for (int j = 0; j < 8; j++)
#pragma unroll
            for (int c = 0; c < 4; c++) s[j][c] *= scale;

        if (jt >= 2 * it) {  // diagonal tiles: global causal mask
            int gr0 = it * 128 + mrow, gr1 = gr0 + 8;
            int gc_base = jt * 64;
#pragma unroll
            for (int j = 0; j < 8; j++) {
                int c0 = gc_base + j * 8 + 2 * lr, c1 = c0 + 1;
                if (c0 > gr0) s[j][0] = -1e30f;
                if (c1 > gr0) s[j][1] = -1e30f;
                if (c0 > gr1) s[j][2] = -1e30f;
                if (c1 > gr1) s[j][3] = -1e30f;
            }
        }

        // ---- online softmax
        float mx0 = -1e30f, mx1 = -1e30f;
#pragma unroll
        for (int j = 0; j < 8; j++) {
            mx0 = fmaxf(mx0, fmaxf(s[j][0], s[j][1]));
            mx1 = fmaxf(mx1, fmaxf(s[j][2], s[j][3]));
        }
        mx0 = fmaxf(mx0, __shfl_xor_sync(0xffffffffu, mx0, 1));
        mx0 = fmaxf(mx0, __shfl_xor_sync(0xffffffffu, mx0, 2));
        mx1 = fmaxf(mx1, __shfl_xor_sync(0xffffffffu, mx1, 1));
        mx1 = fmaxf(mx1, __shfl_xor_sync(0xffffffffu, mx1, 2));

        float mn0 = fmaxf(m0, mx0), mn1 = fmaxf(m1, mx1);
        float f0 = __expf(m0 - mn0), f1 = __expf(m1 - mn1);

        float rs0 = 0.f, rs1 = 0.f;
#pragma unroll
        for (int j = 0; j < 8; j++) {
            s[j][0] = __expf(s[j][0] - mn0);
            s[j][1] = __expf(s[j][1] - mn0);
            s[j][2] = __expf(s[j][2] - mn1);
            s[j][3] = __expf(s[j][3] - mn1);
            rs0 += s[j][0] + s[j][1];
            rs1 += s[j][2] + s[j][3];
        }
        rs0 += __shfl_xor_sync(0xffffffffu, rs0, 1);
        rs0 += __shfl_xor_sync(0xffffffffu, rs0, 2);
        rs1 += __shfl_xor_sync(0xffffffffu, rs1, 1);
        rs1 += __shfl_xor_sync(0xffffffffu, rs1, 2);

        l0 = l0 * f0 + rs0;
        l1 = l1 * f1 + rs1;
        m0 = mn0; m1 = mn1;
#pragma unroll
        for (int j = 0; j < 8; j++) {
            o[j][0] *= f0; o[j][1] *= f0;
            o[j][2] *= f1; o[j][3] *= f1;
        }

        // ---- O += P V  (P packed from registers)
#pragma unroll
        for (int c = 0; c < 4; c++) {
            unsigned a[4];
            a[0] = packh2(s[2 * c][0],     s[2 * c][1]);
            a[1] = packh2(s[2 * c][2],     s[2 * c][3]);
            a[2] = packh2(s[2 * c + 1][0], s[2 * c + 1][1]);
            a[3] = packh2(s[2 * c + 1][2], s[2 * c + 1][3]);
            const int kb = c * 8 + lr;
#pragma unroll
            for (int j = 0; j < 8; j++) {
                unsigned bb[2];
                bb[0] = Vs[kb * 72 + j * 8 + lq];
                bb[1] = Vs[(kb + 4) * 72 + j * 8 + lq];
                mma16h(o[j], a, bb);
            }
        }
    }

    float inv0 = 1.f / l0, inv1 = 1.f / l1;
    size_t row0 = (size_t)b * TT + (size_t)it * 128 + mrow;
    size_t row1 = row0 + 8;
#pragma unroll
    for (int j = 0; j < 8; j++) {
        int cb = h * HSS + j * 8 + 2 * lr;
        *reinterpret_cast<__half2*>(&g_att[row0 * DD + cb]) =
            __floats2half2_rn(o[j][0] * inv0, o[j][1] * inv0);
        *reinterpret_cast<__half2*>(&g_att[row1 * DD + cb]) =
            __floats2half2_rn(o[j][2] * inv1, o[j][3] * inv1);
    }
}

extern "C" void kernel_launch(void* const* d_in, const int* in_sizes, int n_in,
                              void* d_out, int out_size)
{
    const float* x  = (const float*)d_in[0];
    const float* Wq = (const float*)d_in[1];
    const float* Wk = (const float*)d_in[2];
    const float* Wv = (const float*)d_in[3];
    const float* Wo = (const float*)d_in[4];
    const float* bo = (const float*)d_in[5];
    float* out = (float*)d_out;

    cudaFuncSetAttribute(qkv_kernel,
                         cudaFuncAttributeMaxDynamicSharedMemorySize, PIPE_SMEM);
    cudaFuncSetAttribute(proj_kernel,
                         cudaFuncAttributeMaxDynamicSharedMemorySize, PIPE_SMEM);

    conv_kernel<<<512, 256>>>(x, Wq, Wk, Wv, Wo);

    dim3 g1((BB * TT) / 128, 24);
    qkv_kernel<<<g1, 256, PIPE_SMEM>>>();

    dim3 g2(TT / 128, BB * HH);
    attn_kernel<<<g2, 256>>>();

    dim3 g3((BB * TT) / 128, DD / 128);
    proj_kernel<<<g3, 256, PIPE_SMEM>>>(bo, out);
}